// round 3
// baseline (speedup 1.0000x reference)
#include <cuda_runtime.h>
#include <math.h>

// Problem constants (from reference)
#define N_NODES 50000
#define IN_C    512
#define HDIM    256   // H*HID  (layer-1 width)
#define H2DIM   160   // H*OUT_C (layer-2 width)
#define OUT_C   40
#define MAXE    400000

// ---------------------------------------------------------------------------
// Scratch (static device globals — no runtime allocation allowed).
// Referenced DIRECTLY from device code only.
// ---------------------------------------------------------------------------
__device__ float g_h1[(size_t)N_NODES * HDIM];   // x @ W1
__device__ float g_a1[(size_t)N_NODES * HDIM];   // elu(attn1 + b1)
__device__ float g_h2[(size_t)N_NODES * H2DIM];  // a1 @ W2
__device__ int   g_cnt[N_NODES];
__device__ int   g_rowptr[N_NODES + 1];
__device__ int   g_wptr[N_NODES];
__device__ int   g_csrsrc[MAXE + N_NODES];

// ---------------------------------------------------------------------------
// CSR construction (dst-sorted adjacency; self loop per node via count init 1)
// edge_index is int32: src = ei[0..E), dst = ei[E..2E)
// ---------------------------------------------------------------------------
__global__ void k_init_cnt() {
    int i = blockIdx.x * blockDim.x + threadIdx.x;
    if (i < N_NODES) g_cnt[i] = 1;  // one self loop per node
}

__global__ void k_hist(const int* __restrict__ ei, int E) {
    int e = blockIdx.x * blockDim.x + threadIdx.x;
    if (e < E) {
        int d = ei[E + e];
        if ((unsigned)d < (unsigned)N_NODES) atomicAdd(&g_cnt[d], 1);
    }
}

__global__ void k_scan(int n) {
    __shared__ int sh[1024];
    __shared__ int carry;
    int tid = threadIdx.x;
    if (tid == 0) carry = 0;
    __syncthreads();
    for (int base = 0; base < n; base += 1024) {
        int i = base + tid;
        int v = (i < n) ? g_cnt[i] : 0;
        sh[tid] = v;
        __syncthreads();
        for (int d = 1; d < 1024; d <<= 1) {
            int t = (tid >= d) ? sh[tid - d] : 0;
            __syncthreads();
            sh[tid] += t;
            __syncthreads();
        }
        int excl = sh[tid] - v + carry;
        if (i < n) { g_rowptr[i] = excl; g_wptr[i] = excl; }
        int btot = sh[1023];
        __syncthreads();
        if (tid == 0) carry += btot;
        __syncthreads();
    }
    if (tid == 0) g_rowptr[n] = carry;
}

__global__ void k_scatter(const int* __restrict__ ei, int E) {
    int e = blockIdx.x * blockDim.x + threadIdx.x;
    int total = E + N_NODES;
    if (e >= total) return;
    int s, d;
    if (e < E) { s = ei[e]; d = ei[E + e]; }
    else       { s = d = e - E; }
    if ((unsigned)d >= (unsigned)N_NODES || (unsigned)s >= (unsigned)N_NODES) return;
    int pos = atomicAdd(&g_wptr[d], 1);
    if ((unsigned)pos < (unsigned)(MAXE + N_NODES)) g_csrsrc[pos] = s;
}

// ---------------------------------------------------------------------------
// Tiled fp32 SGEMM device body: C[M,Nc] = A[M,K] @ B[K,Nc]  (row-major)
// BM=128, BN=128, BK=16, 8x8 microtile, 256 threads.
// ---------------------------------------------------------------------------
template <int BM, int BN, int BK, int TM, int TN>
__device__ __forceinline__ void sgemm_body(const float* __restrict__ A,
                                           const float* __restrict__ B,
                                           float* __restrict__ C,
                                           int M, int Nc, int K) {
    constexpr int THREADS = (BM / TM) * (BN / TN);
    __shared__ float As[BK][BM + 4];
    __shared__ float Bs[BK][BN];

    int tid  = threadIdx.x;
    int tcol = tid % (BN / TN);
    int trow = tid / (BN / TN);
    int bm = blockIdx.y * BM;
    int bn = blockIdx.x * BN;

    float acc[TM][TN];
#pragma unroll
    for (int i = 0; i < TM; i++)
#pragma unroll
        for (int j = 0; j < TN; j++) acc[i][j] = 0.f;

    for (int kk = 0; kk < K; kk += BK) {
#pragma unroll
        for (int i = tid; i < BM * BK; i += THREADS) {
            int r = i / BK, c = i % BK;
            int gr = bm + r;
            As[c][r] = (gr < M) ? A[(size_t)gr * K + kk + c] : 0.f;
        }
#pragma unroll
        for (int i = tid; i < BK * BN; i += THREADS) {
            int r = i / BN, c = i % BN;
            int gc = bn + c;
            Bs[r][c] = (gc < Nc) ? B[(size_t)(kk + r) * Nc + gc] : 0.f;
        }
        __syncthreads();
#pragma unroll
        for (int k = 0; k < BK; k++) {
            float a[TM], b[TN];
#pragma unroll
            for (int i = 0; i < TM; i++) a[i] = As[k][trow * TM + i];
#pragma unroll
            for (int j = 0; j < TN; j++) b[j] = Bs[k][tcol * TN + j];
#pragma unroll
            for (int i = 0; i < TM; i++)
#pragma unroll
                for (int j = 0; j < TN; j++)
                    acc[i][j] = fmaf(a[i], b[j], acc[i][j]);
        }
        __syncthreads();
    }

#pragma unroll
    for (int i = 0; i < TM; i++) {
        int gr = bm + trow * TM + i;
        if (gr >= M) continue;
#pragma unroll
        for (int j = 0; j < TN; j++) {
            int gc = bn + tcol * TN + j;
            if (gc < Nc) C[(size_t)gr * Nc + gc] = acc[i][j];
        }
    }
}

// Wrappers bind the __device__ scratch buffers in device code.
__global__ void k_gemm1(const float* __restrict__ x, const float* __restrict__ W1) {
    sgemm_body<128, 128, 16, 8, 8>(x, W1, g_h1, N_NODES, HDIM, IN_C);
}
__global__ void k_gemm2(const float* __restrict__ W2) {
    sgemm_body<128, 128, 16, 8, 8>(g_a1, W2, g_h2, N_NODES, H2DIM, HDIM);
}

// ---------------------------------------------------------------------------
// Attention layer: one warp per destination node, online segment-softmax.
// Lane l holds feature elements [l*VPL, l*VPL+VPL). Head = 8 lanes.
//   Layer1: CTOT=256, VPL=8  -> elu(out+b1) to g_a1
//   Layer2: CTOT=160, VPL=5  -> head-mean + b2 + log_softmax -> d_out
// ---------------------------------------------------------------------------
template <int CTOT, int VPL, bool FINAL>
__device__ __forceinline__ void attn_body(const float* __restrict__ h,
                                          const float* __restrict__ bias,
                                          float* __restrict__ out) {
    int gw   = (blockIdx.x * blockDim.x + threadIdx.x) >> 5;
    int lane = threadIdx.x & 31;
    if (gw >= N_NODES) return;

    const float* ib = h + (size_t)gw * CTOT + lane * VPL;
    float xi[VPL];
#pragma unroll
    for (int k = 0; k < VPL; k++) xi[k] = ib[k];

    float m = -1e30f, s = 0.f;
    float acc[VPL];
#pragma unroll
    for (int k = 0; k < VPL; k++) acc[k] = 0.f;

    int e0 = g_rowptr[gw], e1 = g_rowptr[gw + 1];
    for (int e = e0; e < e1; e++) {
        int src = g_csrsrc[e];
        const float* jb = h + (size_t)src * CTOT + lane * VPL;
        float xj[VPL];
#pragma unroll
        for (int k = 0; k < VPL; k++) xj[k] = jb[k];
        float d = 0.f;
#pragma unroll
        for (int k = 0; k < VPL; k++) d = fmaf(xi[k], xj[k], d);
        // reduce over the 8 lanes of this head
        d += __shfl_xor_sync(0xffffffffu, d, 1);
        d += __shfl_xor_sync(0xffffffffu, d, 2);
        d += __shfl_xor_sync(0xffffffffu, d, 4);
        float a = d > 0.f ? d : 0.2f * d;   // leaky_relu(0.2)
        float mn = fmaxf(m, a);
        float corr = __expf(m - mn);
        float w = __expf(a - mn);
        s = s * corr + w;
#pragma unroll
        for (int k = 0; k < VPL; k++) acc[k] = fmaf(acc[k], corr, w * xj[k]);
        m = mn;
    }
    float inv = 1.f / (s + 1e-16f);

    if (!FINAL) {
#pragma unroll
        for (int k = 0; k < VPL; k++) {
            float v = acc[k] * inv + bias[lane * VPL + k];
            v = v > 0.f ? v : expm1f(v);   // elu
            out[(size_t)gw * CTOT + lane * VPL + k] = v;
        }
    } else {
        float r[VPL];
#pragma unroll
        for (int k = 0; k < VPL; k++) r[k] = acc[k] * inv;
        // sum the 4 heads: lanes l, l+8, l+16, l+24 -> lane l (l<8)
#pragma unroll
        for (int k = 0; k < VPL; k++) r[k] += __shfl_down_sync(0xffffffffu, r[k], 16);
#pragma unroll
        for (int k = 0; k < VPL; k++) r[k] += __shfl_down_sync(0xffffffffu, r[k], 8);
        float v[VPL];
        float mx = -1e30f;
        if (lane < 8) {
#pragma unroll
            for (int k = 0; k < VPL; k++) {
                v[k] = 0.25f * r[k] + bias[lane * VPL + k];
                mx = fmaxf(mx, v[k]);
            }
        }
        mx = fmaxf(mx, __shfl_xor_sync(0xffffffffu, mx, 1));
        mx = fmaxf(mx, __shfl_xor_sync(0xffffffffu, mx, 2));
        mx = fmaxf(mx, __shfl_xor_sync(0xffffffffu, mx, 4));
        float se = 0.f;
        if (lane < 8) {
#pragma unroll
            for (int k = 0; k < VPL; k++) se += __expf(v[k] - mx);
        }
        se += __shfl_xor_sync(0xffffffffu, se, 1);
        se += __shfl_xor_sync(0xffffffffu, se, 2);
        se += __shfl_xor_sync(0xffffffffu, se, 4);
        float lse = logf(se) + mx;
        if (lane < 8) {
#pragma unroll
            for (int k = 0; k < VPL; k++)
                out[(size_t)gw * OUT_C + lane * VPL + k] = v[k] - lse;
        }
    }
}

__global__ void k_attn1(const float* __restrict__ b1) {
    attn_body<HDIM, 8, false>(g_h1, b1, g_a1);
}
__global__ void k_attn2(const float* __restrict__ b2, float* __restrict__ out) {
    attn_body<H2DIM, 5, true>(g_h2, b2, out);
}

// zero the att_loss tail (indices >= N*OUT_C)
__global__ void k_tail(float* out, int out_size) {
    for (int i = N_NODES * OUT_C + threadIdx.x; i < out_size; i += blockDim.x)
        out[i] = 0.f;
}

// ---------------------------------------------------------------------------
// Launch
// ---------------------------------------------------------------------------
extern "C" void kernel_launch(void* const* d_in, const int* in_sizes, int n_in,
                              void* d_out, int out_size) {
    const float* x  = (const float*)d_in[0];
    const int*   ei = (const int*)d_in[1];     // int32 edge_index [2, E]
    const float* W1 = (const float*)d_in[2];
    const float* b1 = (const float*)d_in[3];
    const float* W2 = (const float*)d_in[4];
    const float* b2 = (const float*)d_in[5];
    float* out = (float*)d_out;
    int E = in_sizes[1] / 2;

    // CSR build
    k_init_cnt<<<(N_NODES + 255) / 256, 256>>>();
    k_hist<<<(E + 255) / 256, 256>>>(ei, E);
    k_scan<<<1, 1024>>>(N_NODES);
    k_scatter<<<(E + N_NODES + 255) / 256, 256>>>(ei, E);

    // Layer 1
    {
        dim3 grid((HDIM + 127) / 128, (N_NODES + 127) / 128);
        k_gemm1<<<grid, 256>>>(x, W1);
    }
    k_attn1<<<(N_NODES + 7) / 8, 256>>>(b1);

    // Layer 2
    {
        dim3 grid((H2DIM + 127) / 128, (N_NODES + 127) / 128);
        k_gemm2<<<grid, 256>>>(W2);
    }
    k_attn2<<<(N_NODES + 7) / 8, 256>>>(b2, out);

    k_tail<<<1, 256>>>(out, out_size);
}

// round 6
// speedup vs baseline: 2.3618x; 2.3618x over previous
#include <cuda_runtime.h>
#include <cuda_bf16.h>
#include <math.h>
#include <stdint.h>

// Problem constants
#define N_NODES 50000
#define IN_C    512
#define HDIM    256   // H*HID
#define H2DIM   160   // H*OUT_C
#define OUT_C   40
#define MAXE    400000
#define MBLK    391   // ceil(50000/128)

// ---------------------------------------------------------------------------
// Scratch (static device globals)
// ---------------------------------------------------------------------------
__device__ float g_h1[(size_t)N_NODES * HDIM];
__device__ float g_h2[(size_t)N_NODES * H2DIM];
__device__ __align__(16) __nv_bfloat16 g_a1_hi[(size_t)N_NODES * HDIM];
__device__ __align__(16) __nv_bfloat16 g_a1_lo[(size_t)N_NODES * HDIM];
__device__ __align__(16) __nv_bfloat16 g_w1t_hi[(size_t)HDIM * IN_C];   // [n][k]
__device__ __align__(16) __nv_bfloat16 g_w1t_lo[(size_t)HDIM * IN_C];
__device__ __align__(16) __nv_bfloat16 g_w2t_hi[(size_t)H2DIM * HDIM];  // [n][k]
__device__ __align__(16) __nv_bfloat16 g_w2t_lo[(size_t)H2DIM * HDIM];
__device__ int g_cnt[N_NODES];
__device__ int g_rowptr[N_NODES + 1];
__device__ int g_wptr[N_NODES];
__device__ int g_csrsrc[MAXE + N_NODES];

// ---------------------------------------------------------------------------
// bf16 mma.sync (family-common ISA; tcgen05 unavailable on compute_103)
// D(16x8,f32) += A(16x16,bf16 row) * B(16x8,bf16 col)
// ---------------------------------------------------------------------------
__device__ __forceinline__ void mma_bf16(float* d, const uint32_t* a, const uint32_t* b) {
    asm volatile(
        "mma.sync.aligned.m16n8k16.row.col.f32.bf16.bf16.f32 "
        "{%0,%1,%2,%3}, {%4,%5,%6,%7}, {%8,%9}, {%0,%1,%2,%3};"
        : "+f"(d[0]), "+f"(d[1]), "+f"(d[2]), "+f"(d[3])
        : "r"(a[0]), "r"(a[1]), "r"(a[2]), "r"(a[3]), "r"(b[0]), "r"(b[1]));
}

// ---------------------------------------------------------------------------
// Weight prep: transpose + bf16 split  W[K][N] -> WT_hi/lo[N][K]
// ---------------------------------------------------------------------------
template <int K, int NC>
__device__ __forceinline__ void prep_body(const float* __restrict__ W,
                                          __nv_bfloat16* __restrict__ Th,
                                          __nv_bfloat16* __restrict__ Tl) {
    int idx = blockIdx.x * blockDim.x + threadIdx.x;
    if (idx >= K * NC) return;
    int k = idx / NC, n = idx % NC;
    float v = W[idx];
    __nv_bfloat16 h = __float2bfloat16(v);
    __nv_bfloat16 l = __float2bfloat16(v - __bfloat162float(h));
    Th[(size_t)n * K + k] = h;
    Tl[(size_t)n * K + k] = l;
}
__global__ void k_prep_w1(const float* __restrict__ W1) { prep_body<IN_C, HDIM>(W1, g_w1t_hi, g_w1t_lo); }
__global__ void k_prep_w2(const float* __restrict__ W2) { prep_body<HDIM, H2DIM>(W2, g_w2t_hi, g_w2t_lo); }

// ---------------------------------------------------------------------------
// CSR construction
// ---------------------------------------------------------------------------
__global__ void k_init_cnt() {
    int i = blockIdx.x * blockDim.x + threadIdx.x;
    if (i < N_NODES) g_cnt[i] = 1;
}
__global__ void k_hist(const int* __restrict__ ei, int E) {
    int e = blockIdx.x * blockDim.x + threadIdx.x;
    if (e < E) {
        int d = ei[E + e];
        if ((unsigned)d < (unsigned)N_NODES) atomicAdd(&g_cnt[d], 1);
    }
}
__global__ void k_scan(int n) {
    __shared__ int sh[1024];
    __shared__ int carry;
    int tid = threadIdx.x;
    if (tid == 0) carry = 0;
    __syncthreads();
    for (int base = 0; base < n; base += 1024) {
        int i = base + tid;
        int v = (i < n) ? g_cnt[i] : 0;
        sh[tid] = v;
        __syncthreads();
        for (int d = 1; d < 1024; d <<= 1) {
            int t = (tid >= d) ? sh[tid - d] : 0;
            __syncthreads();
            sh[tid] += t;
            __syncthreads();
        }
        int excl = sh[tid] - v + carry;
        if (i < n) { g_rowptr[i] = excl; g_wptr[i] = excl; }
        int btot = sh[1023];
        __syncthreads();
        if (tid == 0) carry += btot;
        __syncthreads();
    }
    if (tid == 0) g_rowptr[n] = carry;
}
__global__ void k_scatter(const int* __restrict__ ei, int E) {
    int e = blockIdx.x * blockDim.x + threadIdx.x;
    int total = E + N_NODES;
    if (e >= total) return;
    int s, d;
    if (e < E) { s = ei[e]; d = ei[E + e]; }
    else       { s = d = e - E; }
    if ((unsigned)d >= (unsigned)N_NODES || (unsigned)s >= (unsigned)N_NODES) return;
    int pos = atomicAdd(&g_wptr[d], 1);
    if ((unsigned)pos < (unsigned)(MAXE + N_NODES)) g_csrsrc[pos] = s;
}

// ---------------------------------------------------------------------------
// mma.sync GEMM: C[M, NTOT] = A[M, KTOT] @ BT[N][K]^T, bf16-split, fp32 accum.
// CTA: 256 threads = 8 warps, each warp owns a 16-row stripe of a 128-row
// M-block. BN columns per CTA. BK=32, padded SMEM rows (BKP=40).
// ---------------------------------------------------------------------------
template <int NTOT, int BN, int KTOT, bool AFP32>
__device__ __forceinline__ void gemm_mma_body(const float* __restrict__ Af,
                                              const __nv_bfloat16* __restrict__ Ahi,
                                              const __nv_bfloat16* __restrict__ Alo,
                                              const __nv_bfloat16* __restrict__ Bhi,
                                              const __nv_bfloat16* __restrict__ Blo,
                                              float* __restrict__ Cout, int M) {
    constexpr int BK = 32;
    constexpr int BKP = 40;          // padded row (20 banks) -> conflict-free frags
    constexpr int NF = BN / 8;       // n-fragments per warp
    constexpr int NCH = KTOT / BK;

    __shared__ __nv_bfloat16 As_hi[128 * BKP];
    __shared__ __nv_bfloat16 As_lo[128 * BKP];
    __shared__ __nv_bfloat16 Bs_hi[BN * BKP];
    __shared__ __nv_bfloat16 Bs_lo[BN * BKP];

    const int tid  = threadIdx.x;
    const int w    = tid >> 5;
    const int lane = tid & 31;
    const int g    = lane >> 2;      // 0..7
    const int tig  = lane & 3;       // 0..3
    const int bm   = blockIdx.y * 128;
    const int bn   = blockIdx.x * BN;

    // staging coords (A: 2 threads per row)
    const int srow = tid >> 1, shalf = tid & 1;
    long arow = bm + srow;
    if (arow > M - 1) arow = M - 1;

    float acc[NF][4];
#pragma unroll
    for (int f = 0; f < NF; f++)
#pragma unroll
        for (int q = 0; q < 4; q++) acc[f][q] = 0.f;

    for (int c = 0; c < NCH; c++) {
        // ---- stage A (128 x 32) ----
        if (AFP32) {
            const float4* src = (const float4*)(Af + arow * KTOT + c * BK + shalf * 16);
            union { __nv_bfloat16 b[16]; uint4 u[2]; } ph, pl;
#pragma unroll
            for (int i = 0; i < 4; i++) {
                float4 p = src[i];
                float vv[4] = {p.x, p.y, p.z, p.w};
#pragma unroll
                for (int j = 0; j < 4; j++) {
                    __nv_bfloat16 hb = __float2bfloat16(vv[j]);
                    ph.b[i * 4 + j] = hb;
                    pl.b[i * 4 + j] = __float2bfloat16(vv[j] - __bfloat162float(hb));
                }
            }
            uint4* dh = (uint4*)&As_hi[srow * BKP + shalf * 16];
            uint4* dl = (uint4*)&As_lo[srow * BKP + shalf * 16];
            dh[0] = ph.u[0]; dh[1] = ph.u[1];
            dl[0] = pl.u[0]; dl[1] = pl.u[1];
        } else {
            const uint4* sh = (const uint4*)(Ahi + arow * KTOT + c * BK + shalf * 16);
            const uint4* sl = (const uint4*)(Alo + arow * KTOT + c * BK + shalf * 16);
            uint4* dh = (uint4*)&As_hi[srow * BKP + shalf * 16];
            uint4* dl = (uint4*)&As_lo[srow * BKP + shalf * 16];
            dh[0] = sh[0]; dh[1] = sh[1];
            dl[0] = sl[0]; dl[1] = sl[1];
        }
        // ---- stage B (BN x 32): strided so BN can exceed threads/2 ----
        for (int t = tid; t < 2 * BN; t += 256) {
            int n = t >> 1, h2 = t & 1;
            const uint4* sh = (const uint4*)(Bhi + (size_t)(bn + n) * KTOT + c * BK + h2 * 16);
            const uint4* sl = (const uint4*)(Blo + (size_t)(bn + n) * KTOT + c * BK + h2 * 16);
            uint4* dh = (uint4*)&Bs_hi[n * BKP + h2 * 16];
            uint4* dl = (uint4*)&Bs_lo[n * BKP + h2 * 16];
            dh[0] = sh[0]; dh[1] = sh[1];
            dl[0] = sl[0]; dl[1] = sl[1];
        }
        __syncthreads();

        // ---- compute: 2 k-steps of 16 ----
#pragma unroll
        for (int ks = 0; ks < 2; ks++) {
            const int k0 = ks * 16;
            uint32_t ah[4], al[4];
            const int a00 = (w * 16 + g) * BKP + k0 + tig * 2;
            ah[0] = *(const uint32_t*)&As_hi[a00];
            ah[1] = *(const uint32_t*)&As_hi[a00 + 8 * BKP];
            ah[2] = *(const uint32_t*)&As_hi[a00 + 8];
            ah[3] = *(const uint32_t*)&As_hi[a00 + 8 * BKP + 8];
            al[0] = *(const uint32_t*)&As_lo[a00];
            al[1] = *(const uint32_t*)&As_lo[a00 + 8 * BKP];
            al[2] = *(const uint32_t*)&As_lo[a00 + 8];
            al[3] = *(const uint32_t*)&As_lo[a00 + 8 * BKP + 8];
#pragma unroll
            for (int f = 0; f < NF; f++) {
                const int b00 = (f * 8 + g) * BKP + k0 + tig * 2;
                uint32_t bh[2], bl[2];
                bh[0] = *(const uint32_t*)&Bs_hi[b00];
                bh[1] = *(const uint32_t*)&Bs_hi[b00 + 8];
                bl[0] = *(const uint32_t*)&Bs_lo[b00];
                bl[1] = *(const uint32_t*)&Bs_lo[b00 + 8];
                mma_bf16(acc[f], ah, bh);
                mma_bf16(acc[f], ah, bl);
                mma_bf16(acc[f], al, bh);
            }
        }
        __syncthreads();
    }

    // ---- epilogue ----
    const int row0 = bm + w * 16 + g;
    const int row1 = row0 + 8;
#pragma unroll
    for (int f = 0; f < NF; f++) {
        const int col = bn + f * 8 + tig * 2;
        if (row0 < M) {
            float2 v = {acc[f][0], acc[f][1]};
            *(float2*)(Cout + (size_t)row0 * NTOT + col) = v;
        }
        if (row1 < M) {
            float2 v = {acc[f][2], acc[f][3]};
            *(float2*)(Cout + (size_t)row1 * NTOT + col) = v;
        }
    }
}

__global__ void __launch_bounds__(256, 2)
k_gemm1_mma(const float* __restrict__ x) {
    gemm_mma_body<HDIM, 128, IN_C, true>(x, nullptr, nullptr, g_w1t_hi, g_w1t_lo, g_h1, N_NODES);
}
__global__ void __launch_bounds__(256, 2)
k_gemm2_mma() {
    gemm_mma_body<H2DIM, H2DIM, HDIM, false>(nullptr, g_a1_hi, g_a1_lo, g_w2t_hi, g_w2t_lo, g_h2, N_NODES);
}

// ---------------------------------------------------------------------------
// Attention: one warp per destination node, online segment-softmax.
// ---------------------------------------------------------------------------
template <int CTOT, int VPL, bool FINAL>
__device__ __forceinline__ void attn_body(const float* __restrict__ h,
                                          const float* __restrict__ bias,
                                          float* __restrict__ out) {
    int gw   = (blockIdx.x * blockDim.x + threadIdx.x) >> 5;
    int lane = threadIdx.x & 31;
    if (gw >= N_NODES) return;

    const float* ib = h + (size_t)gw * CTOT + lane * VPL;
    float xi[VPL];
#pragma unroll
    for (int k = 0; k < VPL; k++) xi[k] = ib[k];

    float m = -1e30f, s = 0.f;
    float acc[VPL];
#pragma unroll
    for (int k = 0; k < VPL; k++) acc[k] = 0.f;

    int e0 = g_rowptr[gw], e1 = g_rowptr[gw + 1];
    for (int e = e0; e < e1; e++) {
        int src = g_csrsrc[e];
        const float* jb = h + (size_t)src * CTOT + lane * VPL;
        float xj[VPL];
#pragma unroll
        for (int k = 0; k < VPL; k++) xj[k] = jb[k];
        float d = 0.f;
#pragma unroll
        for (int k = 0; k < VPL; k++) d = fmaf(xi[k], xj[k], d);
        d += __shfl_xor_sync(0xffffffffu, d, 1);
        d += __shfl_xor_sync(0xffffffffu, d, 2);
        d += __shfl_xor_sync(0xffffffffu, d, 4);
        float a = d > 0.f ? d : 0.2f * d;
        float mn = fmaxf(m, a);
        float corr = __expf(m - mn);
        float w = __expf(a - mn);
        s = s * corr + w;
#pragma unroll
        for (int k = 0; k < VPL; k++) acc[k] = fmaf(acc[k], corr, w * xj[k]);
        m = mn;
    }
    float inv = 1.f / (s + 1e-16f);

    if (!FINAL) {
#pragma unroll
        for (int k = 0; k < VPL; k++) {
            float v = acc[k] * inv + bias[lane * VPL + k];
            v = v > 0.f ? v : expm1f(v);
            size_t idx = (size_t)gw * CTOT + lane * VPL + k;
            __nv_bfloat16 hh = __float2bfloat16(v);
            g_a1_hi[idx] = hh;
            g_a1_lo[idx] = __float2bfloat16(v - __bfloat162float(hh));
        }
    } else {
        float r[VPL];
#pragma unroll
        for (int k = 0; k < VPL; k++) r[k] = acc[k] * inv;
#pragma unroll
        for (int k = 0; k < VPL; k++) r[k] += __shfl_down_sync(0xffffffffu, r[k], 16);
#pragma unroll
        for (int k = 0; k < VPL; k++) r[k] += __shfl_down_sync(0xffffffffu, r[k], 8);
        float v[VPL];
        float mx = -1e30f;
        if (lane < 8) {
#pragma unroll
            for (int k = 0; k < VPL; k++) {
                v[k] = 0.25f * r[k] + bias[lane * VPL + k];
                mx = fmaxf(mx, v[k]);
            }
        }
        mx = fmaxf(mx, __shfl_xor_sync(0xffffffffu, mx, 1));
        mx = fmaxf(mx, __shfl_xor_sync(0xffffffffu, mx, 2));
        mx = fmaxf(mx, __shfl_xor_sync(0xffffffffu, mx, 4));
        float se = 0.f;
        if (lane < 8) {
#pragma unroll
            for (int k = 0; k < VPL; k++) se += __expf(v[k] - mx);
        }
        se += __shfl_xor_sync(0xffffffffu, se, 1);
        se += __shfl_xor_sync(0xffffffffu, se, 2);
        se += __shfl_xor_sync(0xffffffffu, se, 4);
        float lse = logf(se) + mx;
        if (lane < 8) {
#pragma unroll
            for (int k = 0; k < VPL; k++)
                out[(size_t)gw * OUT_C + lane * VPL + k] = v[k] - lse;
        }
    }
}

__global__ void k_attn1(const float* __restrict__ b1) {
    attn_body<HDIM, 8, false>(g_h1, b1, nullptr);
}
__global__ void k_attn2(const float* __restrict__ b2, float* __restrict__ out) {
    attn_body<H2DIM, 5, true>(g_h2, b2, out);
}

__global__ void k_tail(float* out, int out_size) {
    for (int i = N_NODES * OUT_C + threadIdx.x; i < out_size; i += blockDim.x)
        out[i] = 0.f;
}

// ---------------------------------------------------------------------------
// Launch
// ---------------------------------------------------------------------------
extern "C" void kernel_launch(void* const* d_in, const int* in_sizes, int n_in,
                              void* d_out, int out_size) {
    const float* x  = (const float*)d_in[0];
    const int*   ei = (const int*)d_in[1];
    const float* W1 = (const float*)d_in[2];
    const float* b1 = (const float*)d_in[3];
    const float* W2 = (const float*)d_in[4];
    const float* b2 = (const float*)d_in[5];
    float* out = (float*)d_out;
    int E = in_sizes[1] / 2;

    // weight prep + CSR build
    k_prep_w1<<<(IN_C * HDIM + 255) / 256, 256>>>(W1);
    k_prep_w2<<<(HDIM * H2DIM + 255) / 256, 256>>>(W2);
    k_init_cnt<<<(N_NODES + 255) / 256, 256>>>();
    k_hist<<<(E + 255) / 256, 256>>>(ei, E);
    k_scan<<<1, 1024>>>(N_NODES);
    k_scatter<<<(E + N_NODES + 255) / 256, 256>>>(ei, E);

    // Layer 1
    {
        dim3 grid(HDIM / 128, MBLK);
        k_gemm1_mma<<<grid, 256>>>(x);
    }
    k_attn1<<<(N_NODES + 7) / 8, 256>>>(b1);

    // Layer 2
    {
        dim3 grid(1, MBLK);
        k_gemm2_mma<<<grid, 256>>>();
    }
    k_attn2<<<(N_NODES + 7) / 8, 256>>>(b2, out);

    k_tail<<<1, 256>>>(out, out_size);
}

// round 7
// speedup vs baseline: 2.7473x; 1.1632x over previous
#include <cuda_runtime.h>
#include <cuda_bf16.h>
#include <math.h>
#include <stdint.h>

// Problem constants
#define N_NODES 50000
#define IN_C    512
#define HDIM    256   // H*HID
#define H2DIM   160   // H*OUT_C
#define OUT_C   40
#define MAXE    400000
#define MBLK    391   // ceil(50000/128)

// ---------------------------------------------------------------------------
// Scratch (static device globals)
// ---------------------------------------------------------------------------
__device__ float g_h1[(size_t)N_NODES * HDIM];
__device__ float g_h2[(size_t)N_NODES * H2DIM];
__device__ __align__(16) __nv_bfloat16 g_x_hi[(size_t)N_NODES * IN_C];
__device__ __align__(16) __nv_bfloat16 g_x_lo[(size_t)N_NODES * IN_C];
__device__ __align__(16) __nv_bfloat16 g_a1_hi[(size_t)N_NODES * HDIM];
__device__ __align__(16) __nv_bfloat16 g_a1_lo[(size_t)N_NODES * HDIM];
__device__ __align__(16) __nv_bfloat16 g_w1t_hi[(size_t)HDIM * IN_C];   // [n][k]
__device__ __align__(16) __nv_bfloat16 g_w1t_lo[(size_t)HDIM * IN_C];
__device__ __align__(16) __nv_bfloat16 g_w2t_hi[(size_t)H2DIM * HDIM];  // [n][k]
__device__ __align__(16) __nv_bfloat16 g_w2t_lo[(size_t)H2DIM * HDIM];
__device__ int g_cnt[N_NODES];
__device__ int g_rowptr[N_NODES + 1];
__device__ int g_wptr[N_NODES];
__device__ int g_csrsrc[MAXE + N_NODES];

// ---------------------------------------------------------------------------
// mma.sync bf16 + cp.async helpers (family-common ISA)
// ---------------------------------------------------------------------------
__device__ __forceinline__ void mma_bf16(float* d, const uint32_t* a, const uint32_t* b) {
    asm volatile(
        "mma.sync.aligned.m16n8k16.row.col.f32.bf16.bf16.f32 "
        "{%0,%1,%2,%3}, {%4,%5,%6,%7}, {%8,%9}, {%0,%1,%2,%3};"
        : "+f"(d[0]), "+f"(d[1]), "+f"(d[2]), "+f"(d[3])
        : "r"(a[0]), "r"(a[1]), "r"(a[2]), "r"(a[3]), "r"(b[0]), "r"(b[1]));
}
__device__ __forceinline__ uint32_t smem_u32(const void* p) {
    uint32_t a;
    asm("{ .reg .u64 t; cvta.to.shared.u64 t, %1; cvt.u32.u64 %0, t; }" : "=r"(a) : "l"(p));
    return a;
}
#define CP_ASYNC16(dst, src) \
    asm volatile("cp.async.ca.shared.global [%0], [%1], 16;" :: "r"(dst), "l"(src))
#define CP_COMMIT()  asm volatile("cp.async.commit_group;" ::: "memory")
#define CP_WAIT(n)   asm volatile("cp.async.wait_group %0;" :: "n"(n) : "memory")

// ---------------------------------------------------------------------------
// Prep: x -> bf16 hi/lo (8 elems/thread)
// ---------------------------------------------------------------------------
__global__ void k_prep_x(const float* __restrict__ x) {
    size_t i = ((size_t)blockIdx.x * 256 + threadIdx.x) * 8;
    if (i >= (size_t)N_NODES * IN_C) return;
    const float4* src = (const float4*)(x + i);
    float4 p = src[0], q = src[1];
    float v[8] = {p.x, p.y, p.z, p.w, q.x, q.y, q.z, q.w};
    union { __nv_bfloat16 b[8]; uint4 u; } hi, lo;
#pragma unroll
    for (int j = 0; j < 8; j++) {
        __nv_bfloat16 h = __float2bfloat16(v[j]);
        hi.b[j] = h;
        lo.b[j] = __float2bfloat16(v[j] - __bfloat162float(h));
    }
    *(uint4*)(g_x_hi + i) = hi.u;
    *(uint4*)(g_x_lo + i) = lo.u;
}

// Weight prep: transpose + bf16 split  W[K][N] -> WT_hi/lo[N][K]
template <int K, int NC>
__device__ __forceinline__ void prep_body(const float* __restrict__ W,
                                          __nv_bfloat16* __restrict__ Th,
                                          __nv_bfloat16* __restrict__ Tl) {
    int idx = blockIdx.x * blockDim.x + threadIdx.x;
    if (idx >= K * NC) return;
    int k = idx / NC, n = idx % NC;
    float v = W[idx];
    __nv_bfloat16 h = __float2bfloat16(v);
    __nv_bfloat16 l = __float2bfloat16(v - __bfloat162float(h));
    Th[(size_t)n * K + k] = h;
    Tl[(size_t)n * K + k] = l;
}
__global__ void k_prep_w1(const float* __restrict__ W1) { prep_body<IN_C, HDIM>(W1, g_w1t_hi, g_w1t_lo); }
__global__ void k_prep_w2(const float* __restrict__ W2) { prep_body<HDIM, H2DIM>(W2, g_w2t_hi, g_w2t_lo); }

// ---------------------------------------------------------------------------
// CSR construction (+ output tail zeroing folded into init)
// ---------------------------------------------------------------------------
__global__ void k_init_cnt(float* out, int out_size) {
    int i = blockIdx.x * blockDim.x + threadIdx.x;
    if (i < N_NODES) g_cnt[i] = 1;
    if (blockIdx.x == 0) {
        for (int j = N_NODES * OUT_C + threadIdx.x; j < out_size; j += blockDim.x)
            out[j] = 0.f;
    }
}
__global__ void k_hist(const int* __restrict__ ei, int E) {
    int e = blockIdx.x * blockDim.x + threadIdx.x;
    if (e < E) {
        int d = ei[E + e];
        if ((unsigned)d < (unsigned)N_NODES) atomicAdd(&g_cnt[d], 1);
    }
}
__global__ void k_scan(int n) {
    __shared__ int sh[1024];
    __shared__ int carry;
    int tid = threadIdx.x;
    if (tid == 0) carry = 0;
    __syncthreads();
    for (int base = 0; base < n; base += 1024) {
        int i = base + tid;
        int v = (i < n) ? g_cnt[i] : 0;
        sh[tid] = v;
        __syncthreads();
        for (int d = 1; d < 1024; d <<= 1) {
            int t = (tid >= d) ? sh[tid - d] : 0;
            __syncthreads();
            sh[tid] += t;
            __syncthreads();
        }
        int excl = sh[tid] - v + carry;
        if (i < n) { g_rowptr[i] = excl; g_wptr[i] = excl; }
        int btot = sh[1023];
        __syncthreads();
        if (tid == 0) carry += btot;
        __syncthreads();
    }
    if (tid == 0) g_rowptr[n] = carry;
}
__global__ void k_scatter(const int* __restrict__ ei, int E) {
    int e = blockIdx.x * blockDim.x + threadIdx.x;
    int total = E + N_NODES;
    if (e >= total) return;
    int s, d;
    if (e < E) { s = ei[e]; d = ei[E + e]; }
    else       { s = d = e - E; }
    if ((unsigned)d >= (unsigned)N_NODES || (unsigned)s >= (unsigned)N_NODES) return;
    int pos = atomicAdd(&g_wptr[d], 1);
    if ((unsigned)pos < (unsigned)(MAXE + N_NODES)) g_csrsrc[pos] = s;
}

// ---------------------------------------------------------------------------
// Double-buffered cp.async mma GEMM.
// C[M, NT] = A[M, KTOT] @ BT[NT][KTOT]^T  (bf16-split hi/lo, fp32 accum)
// One CTA per 128 M-rows (grid.y), full NT width. 8 warps = 2(M) x 4(N):
// each warp computes 4 m16 tiles x (NT/32) n8 fragments. BK=32, BKP=40.
// ---------------------------------------------------------------------------
template <int NT, int KTOT>
__device__ __forceinline__ void gemm_mma_body(const __nv_bfloat16* __restrict__ Ahi,
                                              const __nv_bfloat16* __restrict__ Alo,
                                              const __nv_bfloat16* __restrict__ Bhi,
                                              const __nv_bfloat16* __restrict__ Blo,
                                              float* __restrict__ Cout, int M) {
    constexpr int BK  = 32;
    constexpr int NCH = KTOT / BK;
    constexpr int NFW = NT / 32;               // n-frags per warp
    constexpr int AH = 0;                      // byte offsets within a stage
    constexpr int AL = 10240;                  // 128*40*2
    constexpr int BH = 20480;
    constexpr int BL = 20480 + NT * 80;        // NT*40*2
    constexpr int STAGE = 20480 + NT * 160;

    extern __shared__ char sm[];
    const uint32_t smu = smem_u32(sm);

    const int tid  = threadIdx.x;
    const int w    = tid >> 5;
    const int lane = tid & 31;
    const int g    = lane >> 2;
    const int tig  = lane & 3;
    const int wm   = w & 1;                    // M-group (64 rows)
    const int wn   = w >> 1;                   // N-group (NT/4 cols)
    const int bm   = blockIdx.y * 128;

    float acc[4][NFW][4];
#pragma unroll
    for (int t = 0; t < 4; t++)
#pragma unroll
        for (int f = 0; f < NFW; f++)
#pragma unroll
            for (int q = 0; q < 4; q++) acc[t][f][q] = 0.f;

    // ---- staging: one K-chunk (A 128x32 hi+lo, B NTx32 hi+lo) via cp.async ----
    auto stage = [&](int c, int b) {
        const int kk = c * BK;
        const int total = 1024 + NT * 8;       // 16B transactions
        for (int t = tid; t < total; t += 256) {
            const __nv_bfloat16* src;
            uint32_t dst;
            if (t < 1024) {
                int split = t >> 9, idx = t & 511, r = idx >> 2, seg = idx & 3;
                int gr = bm + r; if (gr >= M) gr = M - 1;
                src = (split ? Alo : Ahi) + (size_t)gr * KTOT + kk + seg * 8;
                dst = smu + b * STAGE + (split ? AL : AH) + r * 80 + seg * 16;
            } else {
                int j = t - 1024;
                int split = (j >= NT * 4);
                int idx = split ? j - NT * 4 : j;
                int r = idx >> 2, seg = idx & 3;
                src = (split ? Blo : Bhi) + (size_t)r * KTOT + kk + seg * 8;
                dst = smu + b * STAGE + (split ? BL : BH) + r * 80 + seg * 16;
            }
            CP_ASYNC16(dst, src);
        }
    };

    auto compute = [&](int b) {
        const char* p = sm + b * STAGE;
#pragma unroll
        for (int ks = 0; ks < 2; ks++) {
            const int kb = ks * 32 + tig * 4;  // byte offset within 80B row
            uint32_t ah[4][4], al[4][4];
#pragma unroll
            for (int t = 0; t < 4; t++) {
                const int rb = (wm * 64 + t * 16 + g) * 80 + kb;
                ah[t][0] = *(const uint32_t*)(p + AH + rb);
                ah[t][1] = *(const uint32_t*)(p + AH + rb + 640);
                ah[t][2] = *(const uint32_t*)(p + AH + rb + 16);
                ah[t][3] = *(const uint32_t*)(p + AH + rb + 656);
                al[t][0] = *(const uint32_t*)(p + AL + rb);
                al[t][1] = *(const uint32_t*)(p + AL + rb + 640);
                al[t][2] = *(const uint32_t*)(p + AL + rb + 16);
                al[t][3] = *(const uint32_t*)(p + AL + rb + 656);
            }
#pragma unroll
            for (int f = 0; f < NFW; f++) {
                const int bb = (wn * (NT / 4) + f * 8 + g) * 80 + kb;
                uint32_t bh[2], bl[2];
                bh[0] = *(const uint32_t*)(p + BH + bb);
                bh[1] = *(const uint32_t*)(p + BH + bb + 16);
                bl[0] = *(const uint32_t*)(p + BL + bb);
                bl[1] = *(const uint32_t*)(p + BL + bb + 16);
#pragma unroll
                for (int t = 0; t < 4; t++) {
                    mma_bf16(acc[t][f], ah[t], bh);
                    mma_bf16(acc[t][f], ah[t], bl);
                    mma_bf16(acc[t][f], al[t], bh);
                }
            }
        }
    };

    int buf = 0;
    stage(0, 0);
    CP_COMMIT();
    for (int c = 0; c < NCH; c++) {
        if (c + 1 < NCH) {
            stage(c + 1, buf ^ 1);
            CP_COMMIT();
            CP_WAIT(1);
        } else {
            CP_WAIT(0);
        }
        __syncthreads();
        compute(buf);
        __syncthreads();
        buf ^= 1;
    }

    // ---- epilogue ----
#pragma unroll
    for (int t = 0; t < 4; t++) {
        const int row0 = bm + wm * 64 + t * 16 + g;
        const int row1 = row0 + 8;
#pragma unroll
        for (int f = 0; f < NFW; f++) {
            const int col = wn * (NT / 4) + f * 8 + tig * 2;
            if (row0 < M) {
                float2 v = {acc[t][f][0], acc[t][f][1]};
                *(float2*)(Cout + (size_t)row0 * NT + col) = v;
            }
            if (row1 < M) {
                float2 v = {acc[t][f][2], acc[t][f][3]};
                *(float2*)(Cout + (size_t)row1 * NT + col) = v;
            }
        }
    }
}

__global__ void __launch_bounds__(256, 1)
k_gemm1_mma() {
    gemm_mma_body<HDIM, IN_C>(g_x_hi, g_x_lo, g_w1t_hi, g_w1t_lo, g_h1, N_NODES);
}
__global__ void __launch_bounds__(256, 1)
k_gemm2_mma() {
    gemm_mma_body<H2DIM, HDIM>(g_a1_hi, g_a1_lo, g_w2t_hi, g_w2t_lo, g_h2, N_NODES);
}

// ---------------------------------------------------------------------------
// Attention: one warp per destination node, online segment-softmax.
// ---------------------------------------------------------------------------
template <int CTOT, int VPL, bool FINAL>
__device__ __forceinline__ void attn_body(const float* __restrict__ h,
                                          const float* __restrict__ bias,
                                          float* __restrict__ out) {
    int gw   = (blockIdx.x * blockDim.x + threadIdx.x) >> 5;
    int lane = threadIdx.x & 31;
    if (gw >= N_NODES) return;

    float xi[VPL];
    if (VPL == 8) {
        const float4* p = (const float4*)(h + (size_t)gw * CTOT + lane * 8);
        float4 a = p[0], b = p[1];
        xi[0] = a.x; xi[1] = a.y; xi[2] = a.z; xi[3] = a.w;
        xi[4] = b.x; xi[5] = b.y; xi[6] = b.z; xi[7] = b.w;
    } else {
        const float* ib = h + (size_t)gw * CTOT + lane * VPL;
#pragma unroll
        for (int k = 0; k < VPL; k++) xi[k] = ib[k];
    }

    float m = -1e30f, s = 0.f;
    float acc[VPL];
#pragma unroll
    for (int k = 0; k < VPL; k++) acc[k] = 0.f;

    int e0 = g_rowptr[gw], e1 = g_rowptr[gw + 1];
    for (int e = e0; e < e1; e++) {
        int src = g_csrsrc[e];
        float xj[VPL];
        if (VPL == 8) {
            const float4* p = (const float4*)(h + (size_t)src * CTOT + lane * 8);
            float4 a = p[0], b = p[1];
            xj[0] = a.x; xj[1] = a.y; xj[2] = a.z; xj[3] = a.w;
            xj[4] = b.x; xj[5] = b.y; xj[6] = b.z; xj[7] = b.w;
        } else {
            const float* jb = h + (size_t)src * CTOT + lane * VPL;
#pragma unroll
            for (int k = 0; k < VPL; k++) xj[k] = jb[k];
        }
        float d = 0.f;
#pragma unroll
        for (int k = 0; k < VPL; k++) d = fmaf(xi[k], xj[k], d);
        d += __shfl_xor_sync(0xffffffffu, d, 1);
        d += __shfl_xor_sync(0xffffffffu, d, 2);
        d += __shfl_xor_sync(0xffffffffu, d, 4);
        float a = d > 0.f ? d : 0.2f * d;
        float mn = fmaxf(m, a);
        float corr = __expf(m - mn);
        float wgt = __expf(a - mn);
        s = s * corr + wgt;
#pragma unroll
        for (int k = 0; k < VPL; k++) acc[k] = fmaf(acc[k], corr, wgt * xj[k]);
        m = mn;
    }
    float inv = 1.f / (s + 1e-16f);

    if (!FINAL) {
#pragma unroll
        for (int k = 0; k < VPL; k++) {
            float v = acc[k] * inv + bias[lane * VPL + k];
            v = v > 0.f ? v : expm1f(v);
            size_t idx = (size_t)gw * CTOT + lane * VPL + k;
            __nv_bfloat16 hh = __float2bfloat16(v);
            g_a1_hi[idx] = hh;
            g_a1_lo[idx] = __float2bfloat16(v - __bfloat162float(hh));
        }
    } else {
        float r[VPL];
#pragma unroll
        for (int k = 0; k < VPL; k++) r[k] = acc[k] * inv;
#pragma unroll
        for (int k = 0; k < VPL; k++) r[k] += __shfl_down_sync(0xffffffffu, r[k], 16);
#pragma unroll
        for (int k = 0; k < VPL; k++) r[k] += __shfl_down_sync(0xffffffffu, r[k], 8);
        float v[VPL];
        float mx = -1e30f;
        if (lane < 8) {
#pragma unroll
            for (int k = 0; k < VPL; k++) {
                v[k] = 0.25f * r[k] + bias[lane * VPL + k];
                mx = fmaxf(mx, v[k]);
            }
        }
        mx = fmaxf(mx, __shfl_xor_sync(0xffffffffu, mx, 1));
        mx = fmaxf(mx, __shfl_xor_sync(0xffffffffu, mx, 2));
        mx = fmaxf(mx, __shfl_xor_sync(0xffffffffu, mx, 4));
        float se = 0.f;
        if (lane < 8) {
#pragma unroll
            for (int k = 0; k < VPL; k++) se += __expf(v[k] - mx);
        }
        se += __shfl_xor_sync(0xffffffffu, se, 1);
        se += __shfl_xor_sync(0xffffffffu, se, 2);
        se += __shfl_xor_sync(0xffffffffu, se, 4);
        float lse = logf(se) + mx;
        if (lane < 8) {
#pragma unroll
            for (int k = 0; k < VPL; k++)
                out[(size_t)gw * OUT_C + lane * VPL + k] = v[k] - lse;
        }
    }
}

__global__ void k_attn1(const float* __restrict__ b1) {
    attn_body<HDIM, 8, false>(g_h1, b1, nullptr);
}
__global__ void k_attn2(const float* __restrict__ b2, float* __restrict__ out) {
    attn_body<H2DIM, 5, true>(g_h2, b2, out);
}

// ---------------------------------------------------------------------------
// Launch
// ---------------------------------------------------------------------------
extern "C" void kernel_launch(void* const* d_in, const int* in_sizes, int n_in,
                              void* d_out, int out_size) {
    const float* x  = (const float*)d_in[0];
    const int*   ei = (const int*)d_in[1];
    const float* W1 = (const float*)d_in[2];
    const float* b1 = (const float*)d_in[3];
    const float* W2 = (const float*)d_in[4];
    const float* b2 = (const float*)d_in[5];
    float* out = (float*)d_out;
    int E = in_sizes[1] / 2;

    const int SMEM1 = 2 * (20480 + HDIM * 160);   // 122880
    const int SMEM2 = 2 * (20480 + H2DIM * 160);  // 92160
    cudaFuncSetAttribute(k_gemm1_mma, cudaFuncAttributeMaxDynamicSharedMemorySize, SMEM1);
    cudaFuncSetAttribute(k_gemm2_mma, cudaFuncAttributeMaxDynamicSharedMemorySize, SMEM2);

    // prep + CSR build
    k_prep_x<<<(N_NODES * IN_C / 8 + 255) / 256, 256>>>(x);
    k_prep_w1<<<(IN_C * HDIM + 255) / 256, 256>>>(W1);
    k_prep_w2<<<(HDIM * H2DIM + 255) / 256, 256>>>(W2);
    k_init_cnt<<<(N_NODES + 255) / 256, 256>>>(out, out_size);
    k_hist<<<(E + 255) / 256, 256>>>(ei, E);
    k_scan<<<1, 1024>>>(N_NODES);
    k_scatter<<<(E + N_NODES + 255) / 256, 256>>>(ei, E);

    // Layer 1
    k_gemm1_mma<<<dim3(1, MBLK), 256, SMEM1>>>();
    k_attn1<<<(N_NODES + 7) / 8, 256>>>(b1);

    // Layer 2
    k_gemm2_mma<<<dim3(1, MBLK), 256, SMEM2>>>();
    k_attn2<<<(N_NODES + 7) / 8, 256>>>(b2, out);
}

// round 8
// speedup vs baseline: 2.8513x; 1.0379x over previous
#include <cuda_runtime.h>
#include <cuda_bf16.h>
#include <math.h>
#include <stdint.h>

// Problem constants
#define N_NODES 50000
#define IN_C    512
#define HDIM    256   // H*HID
#define H2DIM   160   // H*OUT_C
#define OUT_C   40
#define MAXE    400000
#define MBLK    391   // ceil(50000/128)

// ---------------------------------------------------------------------------
// Scratch (static device globals)
// ---------------------------------------------------------------------------
__device__ float g_h1[(size_t)N_NODES * HDIM];
__device__ float g_h2[(size_t)N_NODES * H2DIM];
__device__ __align__(16) __nv_bfloat16 g_x_hi[(size_t)N_NODES * IN_C];
__device__ __align__(16) __nv_bfloat16 g_x_lo[(size_t)N_NODES * IN_C];
__device__ __align__(16) __nv_bfloat16 g_a1_hi[(size_t)N_NODES * HDIM];
__device__ __align__(16) __nv_bfloat16 g_a1_lo[(size_t)N_NODES * HDIM];
__device__ __align__(16) __nv_bfloat16 g_w1t_hi[(size_t)HDIM * IN_C];   // [n][k]
__device__ __align__(16) __nv_bfloat16 g_w1t_lo[(size_t)HDIM * IN_C];
__device__ __align__(16) __nv_bfloat16 g_w2t_hi[(size_t)H2DIM * HDIM];  // [n][k]
__device__ __align__(16) __nv_bfloat16 g_w2t_lo[(size_t)H2DIM * HDIM];
__device__ int g_cnt[N_NODES];
__device__ int g_rowptr[N_NODES + 1];
__device__ int g_wptr[N_NODES];
__device__ int g_csrsrc[MAXE + N_NODES];

// ---------------------------------------------------------------------------
// mma.sync bf16 + cp.async helpers (family-common ISA)
// ---------------------------------------------------------------------------
__device__ __forceinline__ void mma_bf16(float* d, const uint32_t* a, const uint32_t* b) {
    asm volatile(
        "mma.sync.aligned.m16n8k16.row.col.f32.bf16.bf16.f32 "
        "{%0,%1,%2,%3}, {%4,%5,%6,%7}, {%8,%9}, {%0,%1,%2,%3};"
        : "+f"(d[0]), "+f"(d[1]), "+f"(d[2]), "+f"(d[3])
        : "r"(a[0]), "r"(a[1]), "r"(a[2]), "r"(a[3]), "r"(b[0]), "r"(b[1]));
}
__device__ __forceinline__ uint32_t smem_u32(const void* p) {
    uint32_t a;
    asm("{ .reg .u64 t; cvta.to.shared.u64 t, %1; cvt.u32.u64 %0, t; }" : "=r"(a) : "l"(p));
    return a;
}
#define CP_ASYNC16(dst, src) \
    asm volatile("cp.async.ca.shared.global [%0], [%1], 16;" :: "r"(dst), "l"(src))
#define CP_COMMIT()  asm volatile("cp.async.commit_group;" ::: "memory")
#define CP_WAIT(n)   asm volatile("cp.async.wait_group %0;" :: "n"(n) : "memory")

// ---------------------------------------------------------------------------
// Prep: x -> bf16 hi/lo (8 elems/thread)
// ---------------------------------------------------------------------------
__global__ void k_prep_x(const float* __restrict__ x) {
    size_t i = ((size_t)blockIdx.x * 256 + threadIdx.x) * 8;
    if (i >= (size_t)N_NODES * IN_C) return;
    const float4* src = (const float4*)(x + i);
    float4 p = src[0], q = src[1];
    float v[8] = {p.x, p.y, p.z, p.w, q.x, q.y, q.z, q.w};
    union { __nv_bfloat16 b[8]; uint4 u; } hi, lo;
#pragma unroll
    for (int j = 0; j < 8; j++) {
        __nv_bfloat16 h = __float2bfloat16(v[j]);
        hi.b[j] = h;
        lo.b[j] = __float2bfloat16(v[j] - __bfloat162float(h));
    }
    *(uint4*)(g_x_hi + i) = hi.u;
    *(uint4*)(g_x_lo + i) = lo.u;
}

// Fused weight prep: transpose + bf16 split for W1 and W2 in one launch.
__global__ void k_prep_w(const float* __restrict__ W1, const float* __restrict__ W2) {
    int idx = blockIdx.x * blockDim.x + threadIdx.x;
    const int N1 = IN_C * HDIM;
    if (idx < N1) {
        int k = idx / HDIM, n = idx % HDIM;
        float v = W1[idx];
        __nv_bfloat16 h = __float2bfloat16(v);
        g_w1t_hi[(size_t)n * IN_C + k] = h;
        g_w1t_lo[(size_t)n * IN_C + k] = __float2bfloat16(v - __bfloat162float(h));
    } else if (idx < N1 + HDIM * H2DIM) {
        int j = idx - N1;
        int k = j / H2DIM, n = j % H2DIM;
        float v = W2[j];
        __nv_bfloat16 h = __float2bfloat16(v);
        g_w2t_hi[(size_t)n * HDIM + k] = h;
        g_w2t_lo[(size_t)n * HDIM + k] = __float2bfloat16(v - __bfloat162float(h));
    }
}

// ---------------------------------------------------------------------------
// CSR construction (+ output tail zeroing folded into init)
// ---------------------------------------------------------------------------
__global__ void k_init_cnt(float* out, int out_size) {
    int i = blockIdx.x * blockDim.x + threadIdx.x;
    if (i < N_NODES) g_cnt[i] = 1;
    if (blockIdx.x == 0) {
        for (int j = N_NODES * OUT_C + threadIdx.x; j < out_size; j += blockDim.x)
            out[j] = 0.f;
    }
}
__global__ void k_hist(const int* __restrict__ ei, int E) {
    int e = blockIdx.x * blockDim.x + threadIdx.x;
    if (e < E) {
        int d = ei[E + e];
        if ((unsigned)d < (unsigned)N_NODES) atomicAdd(&g_cnt[d], 1);
    }
}

// Single-block scan: 1024 threads x 8 elems/iter, shfl warp-scan (2 syncs/iter).
__global__ void k_scan(int n) {
    __shared__ int wsum[32];
    __shared__ int s_carry;
    const int tid = threadIdx.x;
    const int lane = tid & 31, wrp = tid >> 5;
    if (tid == 0) s_carry = 0;
    __syncthreads();
    for (int base = 0; base < n; base += 8192) {
        int i0 = base + tid * 8;
        int v[8], run = 0;
#pragma unroll
        for (int j = 0; j < 8; j++) {
            int vi = (i0 + j < n) ? g_cnt[i0 + j] : 0;
            v[j] = run;          // exclusive within thread
            run += vi;
        }
        // warp inclusive scan of run
        int inc = run;
#pragma unroll
        for (int d = 1; d < 32; d <<= 1) {
            int t = __shfl_up_sync(0xffffffffu, inc, d);
            if (lane >= d) inc += t;
        }
        if (lane == 31) wsum[wrp] = inc;
        int carry_in = s_carry;
        __syncthreads();
        if (wrp == 0) {
            int wv = (lane < 32) ? wsum[lane] : 0;
            int wi = wv;
#pragma unroll
            for (int d = 1; d < 32; d <<= 1) {
                int t = __shfl_up_sync(0xffffffffu, wi, d);
                if (lane >= d) wi += t;
            }
            wsum[lane] = wi - wv;  // exclusive warp offsets
            if (lane == 31) s_carry = carry_in + wi;  // block total added
        }
        __syncthreads();
        int thr_excl = carry_in + wsum[wrp] + (inc - run);
#pragma unroll
        for (int j = 0; j < 8; j++) {
            int i = i0 + j;
            if (i < n) { g_rowptr[i] = thr_excl + v[j]; g_wptr[i] = thr_excl + v[j]; }
        }
        __syncthreads();
    }
    if (tid == 0) g_rowptr[n] = s_carry;
}

__global__ void k_scatter(const int* __restrict__ ei, int E) {
    int e = blockIdx.x * blockDim.x + threadIdx.x;
    int total = E + N_NODES;
    if (e >= total) return;
    int s, d;
    if (e < E) { s = ei[e]; d = ei[E + e]; }
    else       { s = d = e - E; }
    if ((unsigned)d >= (unsigned)N_NODES || (unsigned)s >= (unsigned)N_NODES) return;
    int pos = atomicAdd(&g_wptr[d], 1);
    if ((unsigned)pos < (unsigned)(MAXE + N_NODES)) g_csrsrc[pos] = s;
}

// ---------------------------------------------------------------------------
// Double-buffered cp.async mma GEMM. 512 threads = 16 warps (4M x 4N).
// Warp (wm, wn): 2 m16 tiles at rows wm*32(+16), NFW n8-frags at cols wn*NT/4.
// C[M, NT] = A[M, KTOT] @ BT[NT][KTOT]^T  (bf16-split hi/lo, fp32 accum)
// ---------------------------------------------------------------------------
template <int NT, int KTOT>
__device__ __forceinline__ void gemm_mma_body(const __nv_bfloat16* __restrict__ Ahi,
                                              const __nv_bfloat16* __restrict__ Alo,
                                              const __nv_bfloat16* __restrict__ Bhi,
                                              const __nv_bfloat16* __restrict__ Blo,
                                              float* __restrict__ Cout, int M) {
    constexpr int BK  = 32;
    constexpr int NCH = KTOT / BK;
    constexpr int NFW = NT / 32;               // n-frags per warp
    constexpr int AH = 0;
    constexpr int AL = 10240;                  // 128*40*2
    constexpr int BH = 20480;
    constexpr int BL = 20480 + NT * 80;
    constexpr int STAGE = 20480 + NT * 160;

    extern __shared__ char sm[];
    const uint32_t smu = smem_u32(sm);

    const int tid  = threadIdx.x;
    const int w    = tid >> 5;
    const int lane = tid & 31;
    const int g    = lane >> 2;
    const int tig  = lane & 3;
    const int wm   = w & 3;                    // 32-row group
    const int wn   = w >> 2;                   // NT/4-col group
    const int bm   = blockIdx.y * 128;

    float acc[2][NFW][4];
#pragma unroll
    for (int t = 0; t < 2; t++)
#pragma unroll
        for (int f = 0; f < NFW; f++)
#pragma unroll
            for (int q = 0; q < 4; q++) acc[t][f][q] = 0.f;

    auto stage = [&](int c, int b) {
        const int kk = c * BK;
        const int total = 1024 + NT * 8;       // 16B transactions
        for (int t = tid; t < total; t += 512) {
            const __nv_bfloat16* src;
            uint32_t dst;
            if (t < 1024) {
                int split = t >> 9, idx = t & 511, r = idx >> 2, seg = idx & 3;
                int gr = bm + r; if (gr >= M) gr = M - 1;
                src = (split ? Alo : Ahi) + (size_t)gr * KTOT + kk + seg * 8;
                dst = smu + b * STAGE + (split ? AL : AH) + r * 80 + seg * 16;
            } else {
                int j = t - 1024;
                int split = (j >= NT * 4);
                int idx = split ? j - NT * 4 : j;
                int r = idx >> 2, seg = idx & 3;
                src = (split ? Blo : Bhi) + (size_t)r * KTOT + kk + seg * 8;
                dst = smu + b * STAGE + (split ? BL : BH) + r * 80 + seg * 16;
            }
            CP_ASYNC16(dst, src);
        }
    };

    auto compute = [&](int b) {
        const char* p = sm + b * STAGE;
#pragma unroll
        for (int ks = 0; ks < 2; ks++) {
            const int kb = ks * 32 + tig * 4;
            uint32_t ah[2][4], al[2][4];
#pragma unroll
            for (int t = 0; t < 2; t++) {
                const int rb = (wm * 32 + t * 16 + g) * 80 + kb;
                ah[t][0] = *(const uint32_t*)(p + AH + rb);
                ah[t][1] = *(const uint32_t*)(p + AH + rb + 640);
                ah[t][2] = *(const uint32_t*)(p + AH + rb + 16);
                ah[t][3] = *(const uint32_t*)(p + AH + rb + 656);
                al[t][0] = *(const uint32_t*)(p + AL + rb);
                al[t][1] = *(const uint32_t*)(p + AL + rb + 640);
                al[t][2] = *(const uint32_t*)(p + AL + rb + 16);
                al[t][3] = *(const uint32_t*)(p + AL + rb + 656);
            }
#pragma unroll
            for (int f = 0; f < NFW; f++) {
                const int bb = (wn * (NT / 4) + f * 8 + g) * 80 + kb;
                uint32_t bh[2], bl[2];
                bh[0] = *(const uint32_t*)(p + BH + bb);
                bh[1] = *(const uint32_t*)(p + BH + bb + 16);
                bl[0] = *(const uint32_t*)(p + BL + bb);
                bl[1] = *(const uint32_t*)(p + BL + bb + 16);
#pragma unroll
                for (int t = 0; t < 2; t++) {
                    mma_bf16(acc[t][f], ah[t], bh);
                    mma_bf16(acc[t][f], ah[t], bl);
                    mma_bf16(acc[t][f], al[t], bh);
                }
            }
        }
    };

    int buf = 0;
    stage(0, 0);
    CP_COMMIT();
    for (int c = 0; c < NCH; c++) {
        if (c + 1 < NCH) {
            stage(c + 1, buf ^ 1);
            CP_COMMIT();
            CP_WAIT(1);
        } else {
            CP_WAIT(0);
        }
        __syncthreads();
        compute(buf);
        __syncthreads();
        buf ^= 1;
    }

    // ---- epilogue ----
#pragma unroll
    for (int t = 0; t < 2; t++) {
        const int row0 = bm + wm * 32 + t * 16 + g;
        const int row1 = row0 + 8;
#pragma unroll
        for (int f = 0; f < NFW; f++) {
            const int col = wn * (NT / 4) + f * 8 + tig * 2;
            if (row0 < M) {
                float2 v = {acc[t][f][0], acc[t][f][1]};
                *(float2*)(Cout + (size_t)row0 * NT + col) = v;
            }
            if (row1 < M) {
                float2 v = {acc[t][f][2], acc[t][f][3]};
                *(float2*)(Cout + (size_t)row1 * NT + col) = v;
            }
        }
    }
}

__global__ void __launch_bounds__(512, 1)
k_gemm1_mma() {
    gemm_mma_body<HDIM, IN_C>(g_x_hi, g_x_lo, g_w1t_hi, g_w1t_lo, g_h1, N_NODES);
}
__global__ void __launch_bounds__(512, 1)
k_gemm2_mma() {
    gemm_mma_body<H2DIM, HDIM>(g_a1_hi, g_a1_lo, g_w2t_hi, g_w2t_lo, g_h2, N_NODES);
}

// ---------------------------------------------------------------------------
// Attention: one warp per destination node, online segment-softmax.
// ---------------------------------------------------------------------------
template <int CTOT, int VPL, bool FINAL>
__device__ __forceinline__ void attn_body(const float* __restrict__ h,
                                          const float* __restrict__ bias,
                                          float* __restrict__ out) {
    int gw   = (blockIdx.x * blockDim.x + threadIdx.x) >> 5;
    int lane = threadIdx.x & 31;
    if (gw >= N_NODES) return;

    float xi[VPL];
    if (VPL == 8) {
        const float4* p = (const float4*)(h + (size_t)gw * CTOT + lane * 8);
        float4 a = p[0], b = p[1];
        xi[0] = a.x; xi[1] = a.y; xi[2] = a.z; xi[3] = a.w;
        xi[4] = b.x; xi[5] = b.y; xi[6] = b.z; xi[7] = b.w;
    } else {
        const float* ib = h + (size_t)gw * CTOT + lane * VPL;
#pragma unroll
        for (int k = 0; k < VPL; k++) xi[k] = ib[k];
    }

    float m = -1e30f, s = 0.f;
    float acc[VPL];
#pragma unroll
    for (int k = 0; k < VPL; k++) acc[k] = 0.f;

    int e0 = g_rowptr[gw], e1 = g_rowptr[gw + 1];
    for (int e = e0; e < e1; e++) {
        int src = g_csrsrc[e];
        float xj[VPL];
        if (VPL == 8) {
            const float4* p = (const float4*)(h + (size_t)src * CTOT + lane * 8);
            float4 a = p[0], b = p[1];
            xj[0] = a.x; xj[1] = a.y; xj[2] = a.z; xj[3] = a.w;
            xj[4] = b.x; xj[5] = b.y; xj[6] = b.z; xj[7] = b.w;
        } else {
            const float* jb = h + (size_t)src * CTOT + lane * VPL;
#pragma unroll
            for (int k = 0; k < VPL; k++) xj[k] = jb[k];
        }
        float d = 0.f;
#pragma unroll
        for (int k = 0; k < VPL; k++) d = fmaf(xi[k], xj[k], d);
        d += __shfl_xor_sync(0xffffffffu, d, 1);
        d += __shfl_xor_sync(0xffffffffu, d, 2);
        d += __shfl_xor_sync(0xffffffffu, d, 4);
        float a = d > 0.f ? d : 0.2f * d;
        float mn = fmaxf(m, a);
        float corr = __expf(m - mn);
        float wgt = __expf(a - mn);
        s = s * corr + wgt;
#pragma unroll
        for (int k = 0; k < VPL; k++) acc[k] = fmaf(acc[k], corr, wgt * xj[k]);
        m = mn;
    }
    float inv = 1.f / (s + 1e-16f);

    if (!FINAL) {
#pragma unroll
        for (int k = 0; k < VPL; k++) {
            float v = acc[k] * inv + bias[lane * VPL + k];
            v = v > 0.f ? v : expm1f(v);
            size_t idx = (size_t)gw * CTOT + lane * VPL + k;
            __nv_bfloat16 hh = __float2bfloat16(v);
            g_a1_hi[idx] = hh;
            g_a1_lo[idx] = __float2bfloat16(v - __bfloat162float(hh));
        }
    } else {
        float r[VPL];
#pragma unroll
        for (int k = 0; k < VPL; k++) r[k] = acc[k] * inv;
#pragma unroll
        for (int k = 0; k < VPL; k++) r[k] += __shfl_down_sync(0xffffffffu, r[k], 16);
#pragma unroll
        for (int k = 0; k < VPL; k++) r[k] += __shfl_down_sync(0xffffffffu, r[k], 8);
        float v[VPL];
        float mx = -1e30f;
        if (lane < 8) {
#pragma unroll
            for (int k = 0; k < VPL; k++) {
                v[k] = 0.25f * r[k] + bias[lane * VPL + k];
                mx = fmaxf(mx, v[k]);
            }
        }
        mx = fmaxf(mx, __shfl_xor_sync(0xffffffffu, mx, 1));
        mx = fmaxf(mx, __shfl_xor_sync(0xffffffffu, mx, 2));
        mx = fmaxf(mx, __shfl_xor_sync(0xffffffffu, mx, 4));
        float se = 0.f;
        if (lane < 8) {
#pragma unroll
            for (int k = 0; k < VPL; k++) se += __expf(v[k] - mx);
        }
        se += __shfl_xor_sync(0xffffffffu, se, 1);
        se += __shfl_xor_sync(0xffffffffu, se, 2);
        se += __shfl_xor_sync(0xffffffffu, se, 4);
        float lse = logf(se) + mx;
        if (lane < 8) {
#pragma unroll
            for (int k = 0; k < VPL; k++)
                out[(size_t)gw * OUT_C + lane * VPL + k] = v[k] - lse;
        }
    }
}

__global__ void k_attn1(const float* __restrict__ b1) {
    attn_body<HDIM, 8, false>(g_h1, b1, nullptr);
}
__global__ void k_attn2(const float* __restrict__ b2, float* __restrict__ out) {
    attn_body<H2DIM, 5, true>(g_h2, b2, out);
}

// ---------------------------------------------------------------------------
// Launch (gemm1 deliberately 4th so the ncu window captures it)
// ---------------------------------------------------------------------------
extern "C" void kernel_launch(void* const* d_in, const int* in_sizes, int n_in,
                              void* d_out, int out_size) {
    const float* x  = (const float*)d_in[0];
    const int*   ei = (const int*)d_in[1];
    const float* W1 = (const float*)d_in[2];
    const float* b1 = (const float*)d_in[3];
    const float* W2 = (const float*)d_in[4];
    const float* b2 = (const float*)d_in[5];
    float* out = (float*)d_out;
    int E = in_sizes[1] / 2;

    const int SMEM1 = 2 * (20480 + HDIM * 160);   // 122880
    const int SMEM2 = 2 * (20480 + H2DIM * 160);  // 92160
    cudaFuncSetAttribute(k_gemm1_mma, cudaFuncAttributeMaxDynamicSharedMemorySize, SMEM1);
    cudaFuncSetAttribute(k_gemm2_mma, cudaFuncAttributeMaxDynamicSharedMemorySize, SMEM2);

    // 1-3: prep (gemm1 deps) + init
    k_prep_x<<<(N_NODES * IN_C / 8 + 255) / 256, 256>>>(x);
    k_prep_w<<<(IN_C * HDIM + HDIM * H2DIM + 255) / 256, 256>>>(W1, W2);
    k_init_cnt<<<(N_NODES + 255) / 256, 256>>>(out, out_size);

    // 4: GEMM1 (profiled launch)
    k_gemm1_mma<<<dim3(1, MBLK), 512, SMEM1>>>();

    // 5-7: CSR build (only needed by attn1)
    k_hist<<<(E + 255) / 256, 256>>>(ei, E);
    k_scan<<<1, 1024>>>(N_NODES);
    k_scatter<<<(E + N_NODES + 255) / 256, 256>>>(ei, E);

    // 8-10: attention + layer 2
    k_attn1<<<(N_NODES + 7) / 8, 256>>>(b1);
    k_gemm2_mma<<<dim3(1, MBLK), 512, SMEM2>>>();
    k_attn2<<<(N_NODES + 7) / 8, 256>>>(b2, out);
}

// round 9
// speedup vs baseline: 2.8922x; 1.0143x over previous
#include <cuda_runtime.h>
#include <cuda_bf16.h>
#include <math.h>
#include <stdint.h>

// Problem constants
#define N_NODES 50000
#define IN_C    512
#define HDIM    256   // H*HID
#define H2DIM   160   // H*OUT_C
#define OUT_C   40
#define MAXE    400000
#define MBLK    391   // ceil(50000/128)

// ---------------------------------------------------------------------------
// Scratch (static device globals)
// ---------------------------------------------------------------------------
__device__ float g_h1[(size_t)N_NODES * HDIM];
__device__ float g_h2[(size_t)N_NODES * H2DIM];
__device__ __align__(16) __nv_bfloat16 g_x_hi[(size_t)N_NODES * IN_C];
__device__ __align__(16) __nv_bfloat16 g_x_lo[(size_t)N_NODES * IN_C];
__device__ __align__(16) __nv_bfloat16 g_a1_hi[(size_t)N_NODES * HDIM];
__device__ __align__(16) __nv_bfloat16 g_a1_lo[(size_t)N_NODES * HDIM];
__device__ __align__(16) __nv_bfloat16 g_w1t_hi[(size_t)HDIM * IN_C];   // [n][k]
__device__ __align__(16) __nv_bfloat16 g_w1t_lo[(size_t)HDIM * IN_C];
__device__ __align__(16) __nv_bfloat16 g_w2t_hi[(size_t)H2DIM * HDIM];  // [n][k]
__device__ __align__(16) __nv_bfloat16 g_w2t_lo[(size_t)H2DIM * HDIM];
__device__ int g_cnt[N_NODES];
__device__ int g_rowptr[N_NODES + 1];
__device__ int g_wptr[N_NODES];
__device__ int g_csrsrc[MAXE + N_NODES];

// ---------------------------------------------------------------------------
// mma.sync bf16 + ldmatrix + cp.async helpers (family-common ISA)
// ---------------------------------------------------------------------------
__device__ __forceinline__ void mma_bf16(float* d, const uint32_t* a, const uint32_t* b) {
    asm volatile(
        "mma.sync.aligned.m16n8k16.row.col.f32.bf16.bf16.f32 "
        "{%0,%1,%2,%3}, {%4,%5,%6,%7}, {%8,%9}, {%0,%1,%2,%3};"
        : "+f"(d[0]), "+f"(d[1]), "+f"(d[2]), "+f"(d[3])
        : "r"(a[0]), "r"(a[1]), "r"(a[2]), "r"(a[3]), "r"(b[0]), "r"(b[1]));
}
__device__ __forceinline__ void ldsm_x4(uint32_t* r, uint32_t addr) {
    asm volatile("ldmatrix.sync.aligned.m8n8.x4.shared.b16 {%0,%1,%2,%3}, [%4];"
        : "=r"(r[0]), "=r"(r[1]), "=r"(r[2]), "=r"(r[3]) : "r"(addr));
}
__device__ __forceinline__ void ldsm_x2(uint32_t* r, uint32_t addr) {
    asm volatile("ldmatrix.sync.aligned.m8n8.x2.shared.b16 {%0,%1}, [%2];"
        : "=r"(r[0]), "=r"(r[1]) : "r"(addr));
}
__device__ __forceinline__ uint32_t smem_u32(const void* p) {
    uint32_t a;
    asm("{ .reg .u64 t; cvta.to.shared.u64 t, %1; cvt.u32.u64 %0, t; }" : "=r"(a) : "l"(p));
    return a;
}
#define CP_ASYNC16(dst, src) \
    asm volatile("cp.async.ca.shared.global [%0], [%1], 16;" :: "r"(dst), "l"(src))
#define CP_COMMIT()  asm volatile("cp.async.commit_group;" ::: "memory")
#define CP_WAIT(n)   asm volatile("cp.async.wait_group %0;" :: "n"(n) : "memory")

// ---------------------------------------------------------------------------
// Prep: x -> bf16 hi/lo (8 elems/thread)
// ---------------------------------------------------------------------------
__global__ void k_prep_x(const float* __restrict__ x) {
    size_t i = ((size_t)blockIdx.x * 256 + threadIdx.x) * 8;
    if (i >= (size_t)N_NODES * IN_C) return;
    const float4* src = (const float4*)(x + i);
    float4 p = src[0], q = src[1];
    float v[8] = {p.x, p.y, p.z, p.w, q.x, q.y, q.z, q.w};
    union { __nv_bfloat16 b[8]; uint4 u; } hi, lo;
#pragma unroll
    for (int j = 0; j < 8; j++) {
        __nv_bfloat16 h = __float2bfloat16(v[j]);
        hi.b[j] = h;
        lo.b[j] = __float2bfloat16(v[j] - __bfloat162float(h));
    }
    *(uint4*)(g_x_hi + i) = hi.u;
    *(uint4*)(g_x_lo + i) = lo.u;
}

// Fused weight prep: transpose + bf16 split for W1 and W2 in one launch.
__global__ void k_prep_w(const float* __restrict__ W1, const float* __restrict__ W2) {
    int idx = blockIdx.x * blockDim.x + threadIdx.x;
    const int N1 = IN_C * HDIM;
    if (idx < N1) {
        int k = idx / HDIM, n = idx % HDIM;
        float v = W1[idx];
        __nv_bfloat16 h = __float2bfloat16(v);
        g_w1t_hi[(size_t)n * IN_C + k] = h;
        g_w1t_lo[(size_t)n * IN_C + k] = __float2bfloat16(v - __bfloat162float(h));
    } else if (idx < N1 + HDIM * H2DIM) {
        int j = idx - N1;
        int k = j / H2DIM, n = j % H2DIM;
        float v = W2[j];
        __nv_bfloat16 h = __float2bfloat16(v);
        g_w2t_hi[(size_t)n * HDIM + k] = h;
        g_w2t_lo[(size_t)n * HDIM + k] = __float2bfloat16(v - __bfloat162float(h));
    }
}

// ---------------------------------------------------------------------------
// CSR construction (+ output tail zeroing folded into init)
// ---------------------------------------------------------------------------
__global__ void k_init_cnt(float* out, int out_size) {
    int i = blockIdx.x * blockDim.x + threadIdx.x;
    if (i < N_NODES) g_cnt[i] = 1;
    if (blockIdx.x == 0) {
        for (int j = N_NODES * OUT_C + threadIdx.x; j < out_size; j += blockDim.x)
            out[j] = 0.f;
    }
}
__global__ void k_hist(const int* __restrict__ ei, int E) {
    int e = blockIdx.x * blockDim.x + threadIdx.x;
    if (e < E) {
        int d = ei[E + e];
        if ((unsigned)d < (unsigned)N_NODES) atomicAdd(&g_cnt[d], 1);
    }
}

// Single-block scan: 1024 threads x 8 elems/iter, shfl warp-scan.
__global__ void k_scan(int n) {
    __shared__ int wsum[32];
    __shared__ int s_carry;
    const int tid = threadIdx.x;
    const int lane = tid & 31, wrp = tid >> 5;
    if (tid == 0) s_carry = 0;
    __syncthreads();
    for (int base = 0; base < n; base += 8192) {
        int i0 = base + tid * 8;
        int v[8], run = 0;
#pragma unroll
        for (int j = 0; j < 8; j++) {
            int vi = (i0 + j < n) ? g_cnt[i0 + j] : 0;
            v[j] = run;
            run += vi;
        }
        int inc = run;
#pragma unroll
        for (int d = 1; d < 32; d <<= 1) {
            int t = __shfl_up_sync(0xffffffffu, inc, d);
            if (lane >= d) inc += t;
        }
        if (lane == 31) wsum[wrp] = inc;
        int carry_in = s_carry;
        __syncthreads();
        if (wrp == 0) {
            int wv = wsum[lane];
            int wi = wv;
#pragma unroll
            for (int d = 1; d < 32; d <<= 1) {
                int t = __shfl_up_sync(0xffffffffu, wi, d);
                if (lane >= d) wi += t;
            }
            wsum[lane] = wi - wv;
            if (lane == 31) s_carry = carry_in + wi;
        }
        __syncthreads();
        int thr_excl = carry_in + wsum[wrp] + (inc - run);
#pragma unroll
        for (int j = 0; j < 8; j++) {
            int i = i0 + j;
            if (i < n) { g_rowptr[i] = thr_excl + v[j]; g_wptr[i] = thr_excl + v[j]; }
        }
        __syncthreads();
    }
    if (tid == 0) g_rowptr[n] = s_carry;
}

__global__ void k_scatter(const int* __restrict__ ei, int E) {
    int e = blockIdx.x * blockDim.x + threadIdx.x;
    int total = E + N_NODES;
    if (e >= total) return;
    int s, d;
    if (e < E) { s = ei[e]; d = ei[E + e]; }
    else       { s = d = e - E; }
    if ((unsigned)d >= (unsigned)N_NODES || (unsigned)s >= (unsigned)N_NODES) return;
    int pos = atomicAdd(&g_wptr[d], 1);
    if ((unsigned)pos < (unsigned)(MAXE + N_NODES)) g_csrsrc[pos] = s;
}

// ---------------------------------------------------------------------------
// Double-buffered cp.async mma GEMM with ldmatrix fragment loads.
// 512 threads = 16 warps (4M x 4N). Warp (wm, wn): 2 m16 tiles, NFW n8 frags.
// C[M, NT] = A[M, KTOT] @ BT[NT][KTOT]^T  (bf16-split hi/lo, fp32 accum)
// ---------------------------------------------------------------------------
template <int NT, int KTOT>
__device__ __forceinline__ void gemm_mma_body(const __nv_bfloat16* __restrict__ Ahi,
                                              const __nv_bfloat16* __restrict__ Alo,
                                              const __nv_bfloat16* __restrict__ Bhi,
                                              const __nv_bfloat16* __restrict__ Blo,
                                              float* __restrict__ Cout, int M) {
    constexpr int BK  = 32;
    constexpr int NCH = KTOT / BK;
    constexpr int NFW = NT / 32;               // n-frags per warp
    constexpr int AH = 0;
    constexpr int AL = 10240;                  // 128*40*2
    constexpr int BH = 20480;
    constexpr int BL = 20480 + NT * 80;
    constexpr int STAGE = 20480 + NT * 160;

    extern __shared__ char sm[];
    const uint32_t smu = smem_u32(sm);

    const int tid  = threadIdx.x;
    const int w    = tid >> 5;
    const int lane = tid & 31;
    const int g    = lane >> 2;
    const int tig  = lane & 3;
    const int wm   = w & 3;                    // 32-row group
    const int wn   = w >> 2;                   // NT/4-col group
    const int bm   = blockIdx.y * 128;

    // ldmatrix per-thread address components
    const int a_lr   = lane & 15;              // A row within m16 tile
    const int a_seg  = lane >> 4;              // A k-seg (16B)
    const int b_row  = (lane & 7) + ((lane >> 4) << 3);  // B n-row within n16
    const int b_seg  = (lane >> 3) & 1;        // B k-seg
    const int b2_row = lane & 7;               // x2 variant (lanes 0-15 used)
    const int b2_seg = (lane >> 3) & 1;

    float acc[2][NFW][4];
#pragma unroll
    for (int t = 0; t < 2; t++)
#pragma unroll
        for (int f = 0; f < NFW; f++)
#pragma unroll
            for (int q = 0; q < 4; q++) acc[t][f][q] = 0.f;

    auto stage = [&](int c, int b) {
        const int kk = c * BK;
        const int total = 1024 + NT * 8;       // 16B transactions
        for (int t = tid; t < total; t += 512) {
            const __nv_bfloat16* src;
            uint32_t dst;
            if (t < 1024) {
                int split = t >> 9, idx = t & 511, r = idx >> 2, seg = idx & 3;
                int gr = bm + r; if (gr >= M) gr = M - 1;
                src = (split ? Alo : Ahi) + (size_t)gr * KTOT + kk + seg * 8;
                dst = smu + b * STAGE + (split ? AL : AH) + r * 80 + seg * 16;
            } else {
                int j = t - 1024;
                int split = (j >= NT * 4);
                int idx = split ? j - NT * 4 : j;
                int r = idx >> 2, seg = idx & 3;
                src = (split ? Blo : Bhi) + (size_t)r * KTOT + kk + seg * 8;
                dst = smu + b * STAGE + (split ? BL : BH) + r * 80 + seg * 16;
            }
            CP_ASYNC16(dst, src);
        }
    };

    auto compute = [&](int b) {
        const uint32_t pb = smu + b * STAGE;
#pragma unroll
        for (int ks = 0; ks < 2; ks++) {
            const int kbyte = ks * 32;
            uint32_t ah[2][4], al[2][4];
#pragma unroll
            for (int t = 0; t < 2; t++) {
                uint32_t aoff = (uint32_t)(wm * 32 + t * 16 + a_lr) * 80 + kbyte + a_seg * 16;
                ldsm_x4(ah[t], pb + AH + aoff);
                ldsm_x4(al[t], pb + AL + aoff);
            }
            uint32_t bhf[NFW * 2], blf[NFW * 2];
#pragma unroll
            for (int f2 = 0; f2 < NFW / 2; f2++) {
                uint32_t boff = (uint32_t)(wn * (NT / 4) + f2 * 16 + b_row) * 80 + kbyte + b_seg * 16;
                ldsm_x4(&bhf[f2 * 4], pb + BH + boff);
                ldsm_x4(&blf[f2 * 4], pb + BL + boff);
            }
            if (NFW & 1) {
                uint32_t boff = (uint32_t)(wn * (NT / 4) + (NFW - 1) * 8 + b2_row) * 80 + kbyte + b2_seg * 16;
                ldsm_x2(&bhf[(NFW - 1) * 2], pb + BH + boff);
                ldsm_x2(&blf[(NFW - 1) * 2], pb + BL + boff);
            }
#pragma unroll
            for (int f = 0; f < NFW; f++) {
#pragma unroll
                for (int t = 0; t < 2; t++) {
                    mma_bf16(acc[t][f], ah[t], &bhf[f * 2]);
                    mma_bf16(acc[t][f], ah[t], &blf[f * 2]);
                    mma_bf16(acc[t][f], al[t], &bhf[f * 2]);
                }
            }
        }
    };

    int buf = 0;
    stage(0, 0);
    CP_COMMIT();
    for (int c = 0; c < NCH; c++) {
        if (c + 1 < NCH) {
            stage(c + 1, buf ^ 1);
            CP_COMMIT();
            CP_WAIT(1);
        } else {
            CP_WAIT(0);
        }
        __syncthreads();
        compute(buf);
        __syncthreads();
        buf ^= 1;
    }

    // ---- epilogue ----
#pragma unroll
    for (int t = 0; t < 2; t++) {
        const int row0 = bm + wm * 32 + t * 16 + g;
        const int row1 = row0 + 8;
#pragma unroll
        for (int f = 0; f < NFW; f++) {
            const int col = wn * (NT / 4) + f * 8 + tig * 2;
            if (row0 < M) {
                float2 v = {acc[t][f][0], acc[t][f][1]};
                *(float2*)(Cout + (size_t)row0 * NT + col) = v;
            }
            if (row1 < M) {
                float2 v = {acc[t][f][2], acc[t][f][3]};
                *(float2*)(Cout + (size_t)row1 * NT + col) = v;
            }
        }
    }
}

__global__ void __launch_bounds__(512, 1)
k_gemm1_mma() {
    gemm_mma_body<HDIM, IN_C>(g_x_hi, g_x_lo, g_w1t_hi, g_w1t_lo, g_h1, N_NODES);
}
__global__ void __launch_bounds__(512, 1)
k_gemm2_mma() {
    gemm_mma_body<H2DIM, HDIM>(g_a1_hi, g_a1_lo, g_w2t_hi, g_w2t_lo, g_h2, N_NODES);
}

// ---------------------------------------------------------------------------
// Attention: one warp per destination node, online segment-softmax.
// ---------------------------------------------------------------------------
template <int CTOT, int VPL, bool FINAL>
__device__ __forceinline__ void attn_body(const float* __restrict__ h,
                                          const float* __restrict__ bias,
                                          float* __restrict__ out) {
    int gw   = (blockIdx.x * blockDim.x + threadIdx.x) >> 5;
    int lane = threadIdx.x & 31;
    if (gw >= N_NODES) return;

    float xi[VPL];
    if (VPL == 8) {
        const float4* p = (const float4*)(h + (size_t)gw * CTOT + lane * 8);
        float4 a = p[0], b = p[1];
        xi[0] = a.x; xi[1] = a.y; xi[2] = a.z; xi[3] = a.w;
        xi[4] = b.x; xi[5] = b.y; xi[6] = b.z; xi[7] = b.w;
    } else {
        const float* ib = h + (size_t)gw * CTOT + lane * VPL;
#pragma unroll
        for (int k = 0; k < VPL; k++) xi[k] = ib[k];
    }

    float m = -1e30f, s = 0.f;
    float acc[VPL];
#pragma unroll
    for (int k = 0; k < VPL; k++) acc[k] = 0.f;

    int e0 = g_rowptr[gw], e1 = g_rowptr[gw + 1];
    for (int e = e0; e < e1; e++) {
        int src = g_csrsrc[e];
        float xj[VPL];
        if (VPL == 8) {
            const float4* p = (const float4*)(h + (size_t)src * CTOT + lane * 8);
            float4 a = p[0], b = p[1];
            xj[0] = a.x; xj[1] = a.y; xj[2] = a.z; xj[3] = a.w;
            xj[4] = b.x; xj[5] = b.y; xj[6] = b.z; xj[7] = b.w;
        } else {
            const float* jb = h + (size_t)src * CTOT + lane * VPL;
#pragma unroll
            for (int k = 0; k < VPL; k++) xj[k] = jb[k];
        }
        float d = 0.f;
#pragma unroll
        for (int k = 0; k < VPL; k++) d = fmaf(xi[k], xj[k], d);
        d += __shfl_xor_sync(0xffffffffu, d, 1);
        d += __shfl_xor_sync(0xffffffffu, d, 2);
        d += __shfl_xor_sync(0xffffffffu, d, 4);
        float a = d > 0.f ? d : 0.2f * d;
        float mn = fmaxf(m, a);
        float corr = __expf(m - mn);
        float wgt = __expf(a - mn);
        s = s * corr + wgt;
#pragma unroll
        for (int k = 0; k < VPL; k++) acc[k] = fmaf(acc[k], corr, wgt * xj[k]);
        m = mn;
    }
    float inv = 1.f / (s + 1e-16f);

    if (!FINAL) {
#pragma unroll
        for (int k = 0; k < VPL; k++) {
            float v = acc[k] * inv + bias[lane * VPL + k];
            v = v > 0.f ? v : expm1f(v);
            size_t idx = (size_t)gw * CTOT + lane * VPL + k;
            __nv_bfloat16 hh = __float2bfloat16(v);
            g_a1_hi[idx] = hh;
            g_a1_lo[idx] = __float2bfloat16(v - __bfloat162float(hh));
        }
    } else {
        float r[VPL];
#pragma unroll
        for (int k = 0; k < VPL; k++) r[k] = acc[k] * inv;
#pragma unroll
        for (int k = 0; k < VPL; k++) r[k] += __shfl_down_sync(0xffffffffu, r[k], 16);
#pragma unroll
        for (int k = 0; k < VPL; k++) r[k] += __shfl_down_sync(0xffffffffu, r[k], 8);
        float v[VPL];
        float mx = -1e30f;
        if (lane < 8) {
#pragma unroll
            for (int k = 0; k < VPL; k++) {
                v[k] = 0.25f * r[k] + bias[lane * VPL + k];
                mx = fmaxf(mx, v[k]);
            }
        }
        mx = fmaxf(mx, __shfl_xor_sync(0xffffffffu, mx, 1));
        mx = fmaxf(mx, __shfl_xor_sync(0xffffffffu, mx, 2));
        mx = fmaxf(mx, __shfl_xor_sync(0xffffffffu, mx, 4));
        float se = 0.f;
        if (lane < 8) {
#pragma unroll
            for (int k = 0; k < VPL; k++) se += __expf(v[k] - mx);
        }
        se += __shfl_xor_sync(0xffffffffu, se, 1);
        se += __shfl_xor_sync(0xffffffffu, se, 2);
        se += __shfl_xor_sync(0xffffffffu, se, 4);
        float lse = logf(se) + mx;
        if (lane < 8) {
#pragma unroll
            for (int k = 0; k < VPL; k++)
                out[(size_t)gw * OUT_C + lane * VPL + k] = v[k] - lse;
        }
    }
}

__global__ void k_attn1(const float* __restrict__ b1) {
    attn_body<HDIM, 8, false>(g_h1, b1, nullptr);
}
__global__ void k_attn2(const float* __restrict__ b2, float* __restrict__ out) {
    attn_body<H2DIM, 5, true>(g_h2, b2, out);
}

// ---------------------------------------------------------------------------
// Launch (gemm1 deliberately 4th so the ncu window captures it)
// ---------------------------------------------------------------------------
extern "C" void kernel_launch(void* const* d_in, const int* in_sizes, int n_in,
                              void* d_out, int out_size) {
    const float* x  = (const float*)d_in[0];
    const int*   ei = (const int*)d_in[1];
    const float* W1 = (const float*)d_in[2];
    const float* b1 = (const float*)d_in[3];
    const float* W2 = (const float*)d_in[4];
    const float* b2 = (const float*)d_in[5];
    float* out = (float*)d_out;
    int E = in_sizes[1] / 2;

    const int SMEM1 = 2 * (20480 + HDIM * 160);   // 122880
    const int SMEM2 = 2 * (20480 + H2DIM * 160);  // 92160
    cudaFuncSetAttribute(k_gemm1_mma, cudaFuncAttributeMaxDynamicSharedMemorySize, SMEM1);
    cudaFuncSetAttribute(k_gemm2_mma, cudaFuncAttributeMaxDynamicSharedMemorySize, SMEM2);

    // 1-3: prep (gemm1 deps) + init
    k_prep_x<<<(N_NODES * IN_C / 8 + 255) / 256, 256>>>(x);
    k_prep_w<<<(IN_C * HDIM + HDIM * H2DIM + 255) / 256, 256>>>(W1, W2);
    k_init_cnt<<<(N_NODES + 255) / 256, 256>>>(out, out_size);

    // 4: GEMM1 (profiled launch)
    k_gemm1_mma<<<dim3(1, MBLK), 512, SMEM1>>>();

    // 5-7: CSR build (only needed by attn1)
    k_hist<<<(E + 255) / 256, 256>>>(ei, E);
    k_scan<<<1, 1024>>>(N_NODES);
    k_scatter<<<(E + N_NODES + 255) / 256, 256>>>(ei, E);

    // 8-10: attention + layer 2
    k_attn1<<<(N_NODES + 7) / 8, 256>>>(b1);
    k_gemm2_mma<<<dim3(1, MBLK), 512, SMEM2>>>();
    k_attn2<<<(N_NODES + 7) / 8, 256>>>(b2, out);
}

// round 10
// speedup vs baseline: 2.9805x; 1.0305x over previous
#include <cuda_runtime.h>
#include <cuda_bf16.h>
#include <math.h>
#include <stdint.h>

// Problem constants
#define N_NODES 50000
#define IN_C    512
#define HDIM    256   // H*HID
#define H2DIM   160   // H*OUT_C
#define OUT_C   40
#define MAXE    400000
#define MBLK    391   // ceil(50000/128)

// ---------------------------------------------------------------------------
// Scratch (static device globals)
// ---------------------------------------------------------------------------
__device__ float g_h1[(size_t)N_NODES * HDIM];
__device__ float g_h2[(size_t)N_NODES * H2DIM];
__device__ __align__(16) __nv_bfloat16 g_x_hi[(size_t)N_NODES * IN_C];
__device__ __align__(16) __nv_bfloat16 g_x_lo[(size_t)N_NODES * IN_C];
__device__ __align__(16) __nv_bfloat16 g_a1_hi[(size_t)N_NODES * HDIM];
__device__ __align__(16) __nv_bfloat16 g_a1_lo[(size_t)N_NODES * HDIM];
__device__ __align__(16) __nv_bfloat16 g_w1t_hi[(size_t)HDIM * IN_C];   // [n][k]
__device__ __align__(16) __nv_bfloat16 g_w1t_lo[(size_t)HDIM * IN_C];
__device__ __align__(16) __nv_bfloat16 g_w2t_hi[(size_t)H2DIM * HDIM];  // [n][k]
__device__ __align__(16) __nv_bfloat16 g_w2t_lo[(size_t)H2DIM * HDIM];
__device__ int g_cnt[N_NODES];
__device__ int g_rowptr[N_NODES + 1];
__device__ int g_wptr[N_NODES];
__device__ int g_csrsrc[MAXE + N_NODES];

// ---------------------------------------------------------------------------
// mma.sync bf16 + ldmatrix + cp.async helpers (family-common ISA)
// ---------------------------------------------------------------------------
__device__ __forceinline__ void mma_bf16(float* d, const uint32_t* a, const uint32_t* b) {
    asm volatile(
        "mma.sync.aligned.m16n8k16.row.col.f32.bf16.bf16.f32 "
        "{%0,%1,%2,%3}, {%4,%5,%6,%7}, {%8,%9}, {%0,%1,%2,%3};"
        : "+f"(d[0]), "+f"(d[1]), "+f"(d[2]), "+f"(d[3])
        : "r"(a[0]), "r"(a[1]), "r"(a[2]), "r"(a[3]), "r"(b[0]), "r"(b[1]));
}
__device__ __forceinline__ void ldsm_x4(uint32_t* r, uint32_t addr) {
    asm volatile("ldmatrix.sync.aligned.m8n8.x4.shared.b16 {%0,%1,%2,%3}, [%4];"
        : "=r"(r[0]), "=r"(r[1]), "=r"(r[2]), "=r"(r[3]) : "r"(addr));
}
__device__ __forceinline__ void ldsm_x2(uint32_t* r, uint32_t addr) {
    asm volatile("ldmatrix.sync.aligned.m8n8.x2.shared.b16 {%0,%1}, [%2];"
        : "=r"(r[0]), "=r"(r[1]) : "r"(addr));
}
__device__ __forceinline__ uint32_t smem_u32(const void* p) {
    uint32_t a;
    asm("{ .reg .u64 t; cvta.to.shared.u64 t, %1; cvt.u32.u64 %0, t; }" : "=r"(a) : "l"(p));
    return a;
}
#define CP_ASYNC16(dst, src) \
    asm volatile("cp.async.cg.shared.global [%0], [%1], 16;" :: "r"(dst), "l"(src))
#define CP_COMMIT()  asm volatile("cp.async.commit_group;" ::: "memory")
#define CP_WAIT(n)   asm volatile("cp.async.wait_group %0;" :: "n"(n) : "memory")

// ---------------------------------------------------------------------------
// Prep: x -> bf16 hi/lo (8 elems/thread)
// ---------------------------------------------------------------------------
__global__ void k_prep_x(const float* __restrict__ x) {
    size_t i = ((size_t)blockIdx.x * 256 + threadIdx.x) * 8;
    if (i >= (size_t)N_NODES * IN_C) return;
    const float4* src = (const float4*)(x + i);
    float4 p = src[0], q = src[1];
    float v[8] = {p.x, p.y, p.z, p.w, q.x, q.y, q.z, q.w};
    union { __nv_bfloat16 b[8]; uint4 u; } hi, lo;
#pragma unroll
    for (int j = 0; j < 8; j++) {
        __nv_bfloat16 h = __float2bfloat16(v[j]);
        hi.b[j] = h;
        lo.b[j] = __float2bfloat16(v[j] - __bfloat162float(h));
    }
    *(uint4*)(g_x_hi + i) = hi.u;
    *(uint4*)(g_x_lo + i) = lo.u;
}

// Fused weight prep: transpose + bf16 split for W1 and W2 in one launch.
__global__ void k_prep_w(const float* __restrict__ W1, const float* __restrict__ W2) {
    int idx = blockIdx.x * blockDim.x + threadIdx.x;
    const int N1 = IN_C * HDIM;
    if (idx < N1) {
        int k = idx / HDIM, n = idx % HDIM;
        float v = W1[idx];
        __nv_bfloat16 h = __float2bfloat16(v);
        g_w1t_hi[(size_t)n * IN_C + k] = h;
        g_w1t_lo[(size_t)n * IN_C + k] = __float2bfloat16(v - __bfloat162float(h));
    } else if (idx < N1 + HDIM * H2DIM) {
        int j = idx - N1;
        int k = j / H2DIM, n = j % H2DIM;
        float v = W2[j];
        __nv_bfloat16 h = __float2bfloat16(v);
        g_w2t_hi[(size_t)n * HDIM + k] = h;
        g_w2t_lo[(size_t)n * HDIM + k] = __float2bfloat16(v - __bfloat162float(h));
    }
}

// ---------------------------------------------------------------------------
// CSR construction (+ output tail zeroing folded into init)
// ---------------------------------------------------------------------------
__global__ void k_init_cnt(float* out, int out_size) {
    int i = blockIdx.x * blockDim.x + threadIdx.x;
    if (i < N_NODES) g_cnt[i] = 1;
    if (blockIdx.x == 0) {
        for (int j = N_NODES * OUT_C + threadIdx.x; j < out_size; j += blockDim.x)
            out[j] = 0.f;
    }
}
__global__ void k_hist(const int* __restrict__ ei, int E) {
    int e = blockIdx.x * blockDim.x + threadIdx.x;
    if (e < E) {
        int d = ei[E + e];
        if ((unsigned)d < (unsigned)N_NODES) atomicAdd(&g_cnt[d], 1);
    }
}

// Single-block scan: 1024 threads x 8 elems/iter, shfl warp-scan.
__global__ void k_scan(int n) {
    __shared__ int wsum[32];
    __shared__ int s_carry;
    const int tid = threadIdx.x;
    const int lane = tid & 31, wrp = tid >> 5;
    if (tid == 0) s_carry = 0;
    __syncthreads();
    for (int base = 0; base < n; base += 8192) {
        int i0 = base + tid * 8;
        int v[8], run = 0;
#pragma unroll
        for (int j = 0; j < 8; j++) {
            int vi = (i0 + j < n) ? g_cnt[i0 + j] : 0;
            v[j] = run;
            run += vi;
        }
        int inc = run;
#pragma unroll
        for (int d = 1; d < 32; d <<= 1) {
            int t = __shfl_up_sync(0xffffffffu, inc, d);
            if (lane >= d) inc += t;
        }
        if (lane == 31) wsum[wrp] = inc;
        int carry_in = s_carry;
        __syncthreads();
        if (wrp == 0) {
            int wv = wsum[lane];
            int wi = wv;
#pragma unroll
            for (int d = 1; d < 32; d <<= 1) {
                int t = __shfl_up_sync(0xffffffffu, wi, d);
                if (lane >= d) wi += t;
            }
            wsum[lane] = wi - wv;
            if (lane == 31) s_carry = carry_in + wi;
        }
        __syncthreads();
        int thr_excl = carry_in + wsum[wrp] + (inc - run);
#pragma unroll
        for (int j = 0; j < 8; j++) {
            int i = i0 + j;
            if (i < n) { g_rowptr[i] = thr_excl + v[j]; g_wptr[i] = thr_excl + v[j]; }
        }
        __syncthreads();
    }
    if (tid == 0) g_rowptr[n] = s_carry;
}

__global__ void k_scatter(const int* __restrict__ ei, int E) {
    int e = blockIdx.x * blockDim.x + threadIdx.x;
    int total = E + N_NODES;
    if (e >= total) return;
    int s, d;
    if (e < E) { s = ei[e]; d = ei[E + e]; }
    else       { s = d = e - E; }
    if ((unsigned)d >= (unsigned)N_NODES || (unsigned)s >= (unsigned)N_NODES) return;
    int pos = atomicAdd(&g_wptr[d], 1);
    if ((unsigned)pos < (unsigned)(MAXE + N_NODES)) g_csrsrc[pos] = s;
}

// ---------------------------------------------------------------------------
// Double-buffered cp.async mma GEMM with ldmatrix. 256 threads = 8 warps
// (4M x 2N), sized so TWO CTAs fit per SM (regs 256*128*2 = 64K, SMEM <=
// 164KB) -> cross-CTA overlap hides barriers/waits.
// CTA computes C[bm:bm+128, bn:bn+NT]; NT = NTOT/2 (grid.x = 2).
// ---------------------------------------------------------------------------
template <int NTOT, int NT, int KTOT>
__device__ __forceinline__ void gemm_mma_body(const __nv_bfloat16* __restrict__ Ahi,
                                              const __nv_bfloat16* __restrict__ Alo,
                                              const __nv_bfloat16* __restrict__ Bhi,
                                              const __nv_bfloat16* __restrict__ Blo,
                                              float* __restrict__ Cout, int M) {
    constexpr int BK  = 32;
    constexpr int NCH = KTOT / BK;
    constexpr int NFW = NT / 16;               // n8-frags per warp (half of NT/8)
    constexpr int AH = 0;
    constexpr int AL = 10240;                  // 128*40*2
    constexpr int BH = 20480;
    constexpr int BL = 20480 + NT * 80;
    constexpr int STAGE = 20480 + NT * 160;

    extern __shared__ char sm[];
    const uint32_t smu = smem_u32(sm);

    const int tid  = threadIdx.x;
    const int w    = tid >> 5;
    const int lane = tid & 31;
    const int g    = lane >> 2;
    const int tig  = lane & 3;
    const int wm   = w & 3;                    // 32-row group (4 groups)
    const int wn   = w >> 2;                   // NT/2-col group (2 groups)
    const int bm   = blockIdx.y * 128;
    const int bn   = blockIdx.x * NT;

    // ldmatrix per-thread address components
    const int a_lr   = lane & 15;
    const int a_seg  = lane >> 4;
    const int b_row  = (lane & 7) + ((lane >> 4) << 3);
    const int b_seg  = (lane >> 3) & 1;
    const int b2_row = lane & 7;
    const int b2_seg = (lane >> 3) & 1;

    float acc[2][NFW][4];
#pragma unroll
    for (int t = 0; t < 2; t++)
#pragma unroll
        for (int f = 0; f < NFW; f++)
#pragma unroll
            for (int q = 0; q < 4; q++) acc[t][f][q] = 0.f;

    auto stage = [&](int c, int b) {
        const int kk = c * BK;
        const int total = 1024 + NT * 8;       // 16B transactions
        for (int t = tid; t < total; t += 256) {
            const __nv_bfloat16* src;
            uint32_t dst;
            if (t < 1024) {
                int split = t >> 9, idx = t & 511, r = idx >> 2, seg = idx & 3;
                int gr = bm + r; if (gr >= M) gr = M - 1;
                src = (split ? Alo : Ahi) + (size_t)gr * KTOT + kk + seg * 8;
                dst = smu + b * STAGE + (split ? AL : AH) + r * 80 + seg * 16;
            } else {
                int j = t - 1024;
                int split = (j >= NT * 4);
                int idx = split ? j - NT * 4 : j;
                int r = idx >> 2, seg = idx & 3;
                src = (split ? Blo : Bhi) + (size_t)(bn + r) * KTOT + kk + seg * 8;
                dst = smu + b * STAGE + (split ? BL : BH) + r * 80 + seg * 16;
            }
            CP_ASYNC16(dst, src);
        }
    };

    auto compute = [&](int b) {
        const uint32_t pb = smu + b * STAGE;
#pragma unroll
        for (int ks = 0; ks < 2; ks++) {
            const int kbyte = ks * 32;
            uint32_t ah[2][4], al[2][4];
#pragma unroll
            for (int t = 0; t < 2; t++) {
                uint32_t aoff = (uint32_t)(wm * 32 + t * 16 + a_lr) * 80 + kbyte + a_seg * 16;
                ldsm_x4(ah[t], pb + AH + aoff);
                ldsm_x4(al[t], pb + AL + aoff);
            }
            uint32_t bhf[NFW * 2], blf[NFW * 2];
#pragma unroll
            for (int f2 = 0; f2 < NFW / 2; f2++) {
                uint32_t boff = (uint32_t)(wn * (NT / 2) + f2 * 16 + b_row) * 80 + kbyte + b_seg * 16;
                ldsm_x4(&bhf[f2 * 4], pb + BH + boff);
                ldsm_x4(&blf[f2 * 4], pb + BL + boff);
            }
            if (NFW & 1) {
                uint32_t boff = (uint32_t)(wn * (NT / 2) + (NFW - 1) * 8 + b2_row) * 80 + kbyte + b2_seg * 16;
                ldsm_x2(&bhf[(NFW - 1) * 2], pb + BH + boff);
                ldsm_x2(&blf[(NFW - 1) * 2], pb + BL + boff);
            }
#pragma unroll
            for (int f = 0; f < NFW; f++) {
#pragma unroll
                for (int t = 0; t < 2; t++) {
                    mma_bf16(acc[t][f], ah[t], &bhf[f * 2]);
                    mma_bf16(acc[t][f], ah[t], &blf[f * 2]);
                    mma_bf16(acc[t][f], al[t], &bhf[f * 2]);
                }
            }
        }
    };

    int buf = 0;
    stage(0, 0);
    CP_COMMIT();
    for (int c = 0; c < NCH; c++) {
        if (c + 1 < NCH) {
            stage(c + 1, buf ^ 1);
            CP_COMMIT();
            CP_WAIT(1);
        } else {
            CP_WAIT(0);
        }
        __syncthreads();
        compute(buf);
        __syncthreads();
        buf ^= 1;
    }

    // ---- epilogue ----
#pragma unroll
    for (int t = 0; t < 2; t++) {
        const int row0 = bm + wm * 32 + t * 16 + g;
        const int row1 = row0 + 8;
#pragma unroll
        for (int f = 0; f < NFW; f++) {
            const int col = bn + wn * (NT / 2) + f * 8 + tig * 2;
            if (row0 < M) {
                float2 v = {acc[t][f][0], acc[t][f][1]};
                *(float2*)(Cout + (size_t)row0 * NTOT + col) = v;
            }
            if (row1 < M) {
                float2 v = {acc[t][f][2], acc[t][f][3]};
                *(float2*)(Cout + (size_t)row1 * NTOT + col) = v;
            }
        }
    }
}

__global__ void __launch_bounds__(256, 2)
k_gemm1_mma() {
    gemm_mma_body<HDIM, 128, IN_C>(g_x_hi, g_x_lo, g_w1t_hi, g_w1t_lo, g_h1, N_NODES);
}
__global__ void __launch_bounds__(256, 2)
k_gemm2_mma() {
    gemm_mma_body<H2DIM, 80, HDIM>(g_a1_hi, g_a1_lo, g_w2t_hi, g_w2t_lo, g_h2, N_NODES);
}

// ---------------------------------------------------------------------------
// Attention: one warp per destination node, online segment-softmax.
// ---------------------------------------------------------------------------
template <int CTOT, int VPL, bool FINAL>
__device__ __forceinline__ void attn_body(const float* __restrict__ h,
                                          const float* __restrict__ bias,
                                          float* __restrict__ out) {
    int gw   = (blockIdx.x * blockDim.x + threadIdx.x) >> 5;
    int lane = threadIdx.x & 31;
    if (gw >= N_NODES) return;

    float xi[VPL];
    if (VPL == 8) {
        const float4* p = (const float4*)(h + (size_t)gw * CTOT + lane * 8);
        float4 a = p[0], b = p[1];
        xi[0] = a.x; xi[1] = a.y; xi[2] = a.z; xi[3] = a.w;
        xi[4] = b.x; xi[5] = b.y; xi[6] = b.z; xi[7] = b.w;
    } else {
        const float* ib = h + (size_t)gw * CTOT + lane * VPL;
#pragma unroll
        for (int k = 0; k < VPL; k++) xi[k] = ib[k];
    }

    float m = -1e30f, s = 0.f;
    float acc[VPL];
#pragma unroll
    for (int k = 0; k < VPL; k++) acc[k] = 0.f;

    int e0 = g_rowptr[gw], e1 = g_rowptr[gw + 1];
    for (int e = e0; e < e1; e++) {
        int src = g_csrsrc[e];
        float xj[VPL];
        if (VPL == 8) {
            const float4* p = (const float4*)(h + (size_t)src * CTOT + lane * 8);
            float4 a = p[0], b = p[1];
            xj[0] = a.x; xj[1] = a.y; xj[2] = a.z; xj[3] = a.w;
            xj[4] = b.x; xj[5] = b.y; xj[6] = b.z; xj[7] = b.w;
        } else {
            const float* jb = h + (size_t)src * CTOT + lane * VPL;
#pragma unroll
            for (int k = 0; k < VPL; k++) xj[k] = jb[k];
        }
        float d = 0.f;
#pragma unroll
        for (int k = 0; k < VPL; k++) d = fmaf(xi[k], xj[k], d);
        d += __shfl_xor_sync(0xffffffffu, d, 1);
        d += __shfl_xor_sync(0xffffffffu, d, 2);
        d += __shfl_xor_sync(0xffffffffu, d, 4);
        float a = d > 0.f ? d : 0.2f * d;
        float mn = fmaxf(m, a);
        float corr = __expf(m - mn);
        float wgt = __expf(a - mn);
        s = s * corr + wgt;
#pragma unroll
        for (int k = 0; k < VPL; k++) acc[k] = fmaf(acc[k], corr, wgt * xj[k]);
        m = mn;
    }
    float inv = 1.f / (s + 1e-16f);

    if (!FINAL) {
#pragma unroll
        for (int k = 0; k < VPL; k++) {
            float v = acc[k] * inv + bias[lane * VPL + k];
            v = v > 0.f ? v : expm1f(v);
            size_t idx = (size_t)gw * CTOT + lane * VPL + k;
            __nv_bfloat16 hh = __float2bfloat16(v);
            g_a1_hi[idx] = hh;
            g_a1_lo[idx] = __float2bfloat16(v - __bfloat162float(hh));
        }
    } else {
        float r[VPL];
#pragma unroll
        for (int k = 0; k < VPL; k++) r[k] = acc[k] * inv;
#pragma unroll
        for (int k = 0; k < VPL; k++) r[k] += __shfl_down_sync(0xffffffffu, r[k], 16);
#pragma unroll
        for (int k = 0; k < VPL; k++) r[k] += __shfl_down_sync(0xffffffffu, r[k], 8);
        float v[VPL];
        float mx = -1e30f;
        if (lane < 8) {
#pragma unroll
            for (int k = 0; k < VPL; k++) {
                v[k] = 0.25f * r[k] + bias[lane * VPL + k];
                mx = fmaxf(mx, v[k]);
            }
        }
        mx = fmaxf(mx, __shfl_xor_sync(0xffffffffu, mx, 1));
        mx = fmaxf(mx, __shfl_xor_sync(0xffffffffu, mx, 2));
        mx = fmaxf(mx, __shfl_xor_sync(0xffffffffu, mx, 4));
        float se = 0.f;
        if (lane < 8) {
#pragma unroll
            for (int k = 0; k < VPL; k++) se += __expf(v[k] - mx);
        }
        se += __shfl_xor_sync(0xffffffffu, se, 1);
        se += __shfl_xor_sync(0xffffffffu, se, 2);
        se += __shfl_xor_sync(0xffffffffu, se, 4);
        float lse = logf(se) + mx;
        if (lane < 8) {
#pragma unroll
            for (int k = 0; k < VPL; k++)
                out[(size_t)gw * OUT_C + lane * VPL + k] = v[k] - lse;
        }
    }
}

__global__ void k_attn1(const float* __restrict__ b1) {
    attn_body<HDIM, 8, false>(g_h1, b1, nullptr);
}
__global__ void k_attn2(const float* __restrict__ b2, float* __restrict__ out) {
    attn_body<H2DIM, 5, true>(g_h2, b2, out);
}

// ---------------------------------------------------------------------------
// Launch (gemm1 deliberately 4th so the ncu window captures it)
// ---------------------------------------------------------------------------
extern "C" void kernel_launch(void* const* d_in, const int* in_sizes, int n_in,
                              void* d_out, int out_size) {
    const float* x  = (const float*)d_in[0];
    const int*   ei = (const int*)d_in[1];
    const float* W1 = (const float*)d_in[2];
    const float* b1 = (const float*)d_in[3];
    const float* W2 = (const float*)d_in[4];
    const float* b2 = (const float*)d_in[5];
    float* out = (float*)d_out;
    int E = in_sizes[1] / 2;

    const int SMEM1 = 2 * (20480 + 128 * 160);   // 81920  (x2 CTAs = 163KB/SM)
    const int SMEM2 = 2 * (20480 + 80 * 160);    // 66560  (x2 CTAs = 133KB/SM)
    cudaFuncSetAttribute(k_gemm1_mma, cudaFuncAttributeMaxDynamicSharedMemorySize, SMEM1);
    cudaFuncSetAttribute(k_gemm2_mma, cudaFuncAttributeMaxDynamicSharedMemorySize, SMEM2);

    // 1-3: prep (gemm1 deps) + init
    k_prep_x<<<(N_NODES * IN_C / 8 + 255) / 256, 256>>>(x);
    k_prep_w<<<(IN_C * HDIM + HDIM * H2DIM + 255) / 256, 256>>>(W1, W2);
    k_init_cnt<<<(N_NODES + 255) / 256, 256>>>(out, out_size);

    // 4: GEMM1 (profiled launch)
    k_gemm1_mma<<<dim3(2, MBLK), 256, SMEM1>>>();

    // 5-7: CSR build (only needed by attn1)
    k_hist<<<(E + 255) / 256, 256>>>(ei, E);
    k_scan<<<1, 1024>>>(N_NODES);
    k_scatter<<<(E + N_NODES + 255) / 256, 256>>>(ei, E);

    // 8-10: attention + layer 2
    k_attn1<<<(N_NODES + 7) / 8, 256>>>(b1);
    k_gemm2_mma<<<dim3(2, MBLK), 256, SMEM2>>>();
    k_attn2<<<(N_NODES + 7) / 8, 256>>>(b2, out);
}

// round 11
// speedup vs baseline: 3.1493x; 1.0566x over previous
#include <cuda_runtime.h>
#include <cuda_bf16.h>
#include <math.h>
#include <stdint.h>

// Problem constants
#define N_NODES 50000
#define IN_C    512
#define HDIM    256   // H*HID
#define H2DIM   160   // H*OUT_C
#define OUT_C   40
#define MAXE    400000
#define MBLK    391   // ceil(50000/128)

// ---------------------------------------------------------------------------
// Scratch (static device globals)
// ---------------------------------------------------------------------------
__device__ float g_h1[(size_t)N_NODES * HDIM];
__device__ float g_h2[(size_t)N_NODES * H2DIM];
__device__ __align__(16) __nv_bfloat16 g_a1_hi[(size_t)N_NODES * HDIM];
__device__ __align__(16) __nv_bfloat16 g_a1_lo[(size_t)N_NODES * HDIM];
__device__ __align__(16) __nv_bfloat16 g_w1t_hi[(size_t)HDIM * IN_C];   // [n][k]
__device__ __align__(16) __nv_bfloat16 g_w1t_lo[(size_t)HDIM * IN_C];
__device__ __align__(16) __nv_bfloat16 g_w2t_hi[(size_t)H2DIM * HDIM];  // [n][k]
__device__ __align__(16) __nv_bfloat16 g_w2t_lo[(size_t)H2DIM * HDIM];
__device__ int g_cnt[N_NODES];
__device__ int g_rowptr[N_NODES + 1];
__device__ int g_wptr[N_NODES];
__device__ int g_csrsrc[MAXE + N_NODES];

// ---------------------------------------------------------------------------
// mma.sync bf16 + ldmatrix + cp.async helpers (family-common ISA)
// ---------------------------------------------------------------------------
__device__ __forceinline__ void mma_bf16(float* d, const uint32_t* a, const uint32_t* b) {
    asm volatile(
        "mma.sync.aligned.m16n8k16.row.col.f32.bf16.bf16.f32 "
        "{%0,%1,%2,%3}, {%4,%5,%6,%7}, {%8,%9}, {%0,%1,%2,%3};"
        : "+f"(d[0]), "+f"(d[1]), "+f"(d[2]), "+f"(d[3])
        : "r"(a[0]), "r"(a[1]), "r"(a[2]), "r"(a[3]), "r"(b[0]), "r"(b[1]));
}
__device__ __forceinline__ void ldsm_x4(uint32_t* r, uint32_t addr) {
    asm volatile("ldmatrix.sync.aligned.m8n8.x4.shared.b16 {%0,%1,%2,%3}, [%4];"
        : "=r"(r[0]), "=r"(r[1]), "=r"(r[2]), "=r"(r[3]) : "r"(addr));
}
__device__ __forceinline__ void ldsm_x2(uint32_t* r, uint32_t addr) {
    asm volatile("ldmatrix.sync.aligned.m8n8.x2.shared.b16 {%0,%1}, [%2];"
        : "=r"(r[0]), "=r"(r[1]) : "r"(addr));
}
__device__ __forceinline__ uint32_t smem_u32(const void* p) {
    uint32_t a;
    asm("{ .reg .u64 t; cvta.to.shared.u64 t, %1; cvt.u32.u64 %0, t; }" : "=r"(a) : "l"(p));
    return a;
}
#define CP_ASYNC16(dst, src) \
    asm volatile("cp.async.cg.shared.global [%0], [%1], 16;" :: "r"(dst), "l"(src))
#define CP_COMMIT()  asm volatile("cp.async.commit_group;" ::: "memory")
#define CP_WAIT(n)   asm volatile("cp.async.wait_group %0;" :: "n"(n) : "memory")

// Pack 2 fp32 -> bf16x2 reg (lo element in low 16 bits)
__device__ __forceinline__ uint32_t cvt_bf16x2(float hi_elem, float lo_elem) {
    uint32_t r;
    asm("cvt.rn.bf16x2.f32 %0, %1, %2;" : "=r"(r) : "f"(hi_elem), "f"(lo_elem));
    return r;
}

// ---------------------------------------------------------------------------
// Fused weight prep: transpose + bf16 split for W1 and W2 in one launch.
// ---------------------------------------------------------------------------
__global__ void k_prep_w(const float* __restrict__ W1, const float* __restrict__ W2) {
    int idx = blockIdx.x * blockDim.x + threadIdx.x;
    const int N1 = IN_C * HDIM;
    if (idx < N1) {
        int k = idx / HDIM, n = idx % HDIM;
        float v = W1[idx];
        __nv_bfloat16 h = __float2bfloat16(v);
        g_w1t_hi[(size_t)n * IN_C + k] = h;
        g_w1t_lo[(size_t)n * IN_C + k] = __float2bfloat16(v - __bfloat162float(h));
    } else if (idx < N1 + HDIM * H2DIM) {
        int j = idx - N1;
        int k = j / H2DIM, n = j % H2DIM;
        float v = W2[j];
        __nv_bfloat16 h = __float2bfloat16(v);
        g_w2t_hi[(size_t)n * HDIM + k] = h;
        g_w2t_lo[(size_t)n * HDIM + k] = __float2bfloat16(v - __bfloat162float(h));
    }
}

// ---------------------------------------------------------------------------
// CSR construction (+ output tail zeroing folded into init)
// ---------------------------------------------------------------------------
__global__ void k_init_cnt(float* out, int out_size) {
    int i = blockIdx.x * blockDim.x + threadIdx.x;
    if (i < N_NODES) g_cnt[i] = 1;
    if (blockIdx.x == 0) {
        for (int j = N_NODES * OUT_C + threadIdx.x; j < out_size; j += blockDim.x)
            out[j] = 0.f;
    }
}
__global__ void k_hist(const int* __restrict__ ei, int E) {
    int e = blockIdx.x * blockDim.x + threadIdx.x;
    if (e < E) {
        int d = ei[E + e];
        if ((unsigned)d < (unsigned)N_NODES) atomicAdd(&g_cnt[d], 1);
    }
}

// Single-block scan: 1024 threads x 8 elems/iter, shfl warp-scan.
__global__ void k_scan(int n) {
    __shared__ int wsum[32];
    __shared__ int s_carry;
    const int tid = threadIdx.x;
    const int lane = tid & 31, wrp = tid >> 5;
    if (tid == 0) s_carry = 0;
    __syncthreads();
    for (int base = 0; base < n; base += 8192) {
        int i0 = base + tid * 8;
        int v[8], run = 0;
#pragma unroll
        for (int j = 0; j < 8; j++) {
            int vi = (i0 + j < n) ? g_cnt[i0 + j] : 0;
            v[j] = run;
            run += vi;
        }
        int inc = run;
#pragma unroll
        for (int d = 1; d < 32; d <<= 1) {
            int t = __shfl_up_sync(0xffffffffu, inc, d);
            if (lane >= d) inc += t;
        }
        if (lane == 31) wsum[wrp] = inc;
        int carry_in = s_carry;
        __syncthreads();
        if (wrp == 0) {
            int wv = wsum[lane];
            int wi = wv;
#pragma unroll
            for (int d = 1; d < 32; d <<= 1) {
                int t = __shfl_up_sync(0xffffffffu, wi, d);
                if (lane >= d) wi += t;
            }
            wsum[lane] = wi - wv;
            if (lane == 31) s_carry = carry_in + wi;
        }
        __syncthreads();
        int thr_excl = carry_in + wsum[wrp] + (inc - run);
#pragma unroll
        for (int j = 0; j < 8; j++) {
            int i = i0 + j;
            if (i < n) { g_rowptr[i] = thr_excl + v[j]; g_wptr[i] = thr_excl + v[j]; }
        }
        __syncthreads();
    }
    if (tid == 0) g_rowptr[n] = s_carry;
}

__global__ void k_scatter(const int* __restrict__ ei, int E) {
    int e = blockIdx.x * blockDim.x + threadIdx.x;
    int total = E + N_NODES;
    if (e >= total) return;
    int s, d;
    if (e < E) { s = ei[e]; d = ei[E + e]; }
    else       { s = d = e - E; }
    if ((unsigned)d >= (unsigned)N_NODES || (unsigned)s >= (unsigned)N_NODES) return;
    int pos = atomicAdd(&g_wptr[d], 1);
    if ((unsigned)pos < (unsigned)(MAXE + N_NODES)) g_csrsrc[pos] = s;
}

// ---------------------------------------------------------------------------
// Double-buffered cp.async mma GEMM, 256 threads = 8 warps (4M x 2N),
// two CTAs per SM. CTA computes C[bm:bm+128, bn:bn+NT].
// AFP32: A staged raw fp32 (seg-swizzled) and split to bf16 hi/lo in the
// fragment load (eliminates the prep_x pass). Else A is pre-split bf16.
// ---------------------------------------------------------------------------
template <int NTOT, int NT, int KTOT, bool AFP32>
__device__ __forceinline__ void gemm_mma_body(const float* __restrict__ Af,
                                              const __nv_bfloat16* __restrict__ Ahi,
                                              const __nv_bfloat16* __restrict__ Alo,
                                              const __nv_bfloat16* __restrict__ Bhi,
                                              const __nv_bfloat16* __restrict__ Blo,
                                              float* __restrict__ Cout, int M) {
    constexpr int BK  = 32;
    constexpr int NCH = KTOT / BK;
    constexpr int NFW = NT / 16;               // n8-frags per warp
    // stage layout
    constexpr int AH = 0;                      // bf16-A path offsets
    constexpr int AL = 10240;
    constexpr int BH = AFP32 ? 16384 : 20480;  // fp32 A = 128*128B = 16KB
    constexpr int BL = BH + NT * 80;
    constexpr int STAGE = BH + NT * 160;

    extern __shared__ char sm[];
    const uint32_t smu = smem_u32(sm);

    const int tid  = threadIdx.x;
    const int w    = tid >> 5;
    const int lane = tid & 31;
    const int g    = lane >> 2;
    const int tig  = lane & 3;
    const int wm   = w & 3;                    // 32-row group
    const int wn   = w >> 2;                   // NT/2-col group
    const int bm   = blockIdx.y * 128;
    const int bn   = blockIdx.x * NT;

    // ldmatrix per-thread address components (bf16 paths)
    const int a_lr   = lane & 15;
    const int a_seg  = lane >> 4;
    const int b_row  = (lane & 7) + ((lane >> 4) << 3);
    const int b_seg  = (lane >> 3) & 1;
    const int b2_row = lane & 7;
    const int b2_seg = (lane >> 3) & 1;

    float acc[2][NFW][4];
#pragma unroll
    for (int t = 0; t < 2; t++)
#pragma unroll
        for (int f = 0; f < NFW; f++)
#pragma unroll
            for (int q = 0; q < 4; q++) acc[t][f][q] = 0.f;

    auto stage = [&](int c, int b) {
        const int kk = c * BK;
        const int total = 1024 + NT * 8;       // 16B transactions
        for (int t = tid; t < total; t += 256) {
            if (t < 1024) {
                if (AFP32) {
                    int r = t >> 3, s = t & 7;
                    int gr = bm + r; if (gr >= M) gr = M - 1;
                    const float* src = Af + (size_t)gr * KTOT + kk + s * 4;
                    uint32_t dst = smu + b * STAGE + r * 128 + ((s ^ (r & 7)) << 4);
                    CP_ASYNC16(dst, src);
                } else {
                    int split = t >> 9, idx = t & 511, r = idx >> 2, seg = idx & 3;
                    int gr = bm + r; if (gr >= M) gr = M - 1;
                    const __nv_bfloat16* src = (split ? Alo : Ahi) + (size_t)gr * KTOT + kk + seg * 8;
                    uint32_t dst = smu + b * STAGE + (split ? AL : AH) + r * 80 + seg * 16;
                    CP_ASYNC16(dst, src);
                }
            } else {
                int j = t - 1024;
                int split = (j >= NT * 4);
                int idx = split ? j - NT * 4 : j;
                int r = idx >> 2, seg = idx & 3;
                const __nv_bfloat16* src = (split ? Blo : Bhi) + (size_t)(bn + r) * KTOT + kk + seg * 8;
                uint32_t dst = smu + b * STAGE + (split ? BL : BH) + r * 80 + seg * 16;
                CP_ASYNC16(dst, src);
            }
        }
    };

    auto compute = [&](int b) {
        const uint32_t pb = smu + b * STAGE;
        const char* pc = sm + (size_t)b * STAGE;
#pragma unroll
        for (int ks = 0; ks < 2; ks++) {
            const int kbyte = ks * 32;
            uint32_t ah[2][4], al[2][4];
            if (AFP32) {
                // Build bf16 hi/lo A frags from swizzled fp32 smem.
#pragma unroll
                for (int mt = 0; mt < 2; mt++) {
#pragma unroll
                    for (int j = 0; j < 4; j++) {
                        int row = wm * 32 + mt * 16 + g + ((j & 1) << 3);
                        int s = (tig >> 1) + ((j >> 1) << 1) + (ks << 2);
                        int h = tig & 1;
                        const float2 f = *(const float2*)(pc + row * 128 + ((s ^ g) << 4) + (h << 3));
                        uint32_t hi_ = cvt_bf16x2(f.y, f.x);
                        float h0 = __uint_as_float(hi_ << 16);
                        float h1 = __uint_as_float(hi_ & 0xffff0000u);
                        uint32_t lo_ = cvt_bf16x2(f.y - h1, f.x - h0);
                        ah[mt][j] = hi_;
                        al[mt][j] = lo_;
                    }
                }
            } else {
#pragma unroll
                for (int t = 0; t < 2; t++) {
                    uint32_t aoff = (uint32_t)(wm * 32 + t * 16 + a_lr) * 80 + kbyte + a_seg * 16;
                    ldsm_x4(ah[t], pb + AH + aoff);
                    ldsm_x4(al[t], pb + AL + aoff);
                }
            }
            uint32_t bhf[NFW * 2], blf[NFW * 2];
#pragma unroll
            for (int f2 = 0; f2 < NFW / 2; f2++) {
                uint32_t boff = (uint32_t)(wn * (NT / 2) + f2 * 16 + b_row) * 80 + kbyte + b_seg * 16;
                ldsm_x4(&bhf[f2 * 4], pb + BH + boff);
                ldsm_x4(&blf[f2 * 4], pb + BL + boff);
            }
            if (NFW & 1) {
                uint32_t boff = (uint32_t)(wn * (NT / 2) + (NFW - 1) * 8 + b2_row) * 80 + kbyte + b2_seg * 16;
                ldsm_x2(&bhf[(NFW - 1) * 2], pb + BH + boff);
                ldsm_x2(&blf[(NFW - 1) * 2], pb + BL + boff);
            }
#pragma unroll
            for (int f = 0; f < NFW; f++) {
#pragma unroll
                for (int t = 0; t < 2; t++) {
                    mma_bf16(acc[t][f], ah[t], &bhf[f * 2]);
                    mma_bf16(acc[t][f], ah[t], &blf[f * 2]);
                    mma_bf16(acc[t][f], al[t], &bhf[f * 2]);
                }
            }
        }
    };

    int buf = 0;
    stage(0, 0);
    CP_COMMIT();
    for (int c = 0; c < NCH; c++) {
        if (c + 1 < NCH) {
            stage(c + 1, buf ^ 1);
            CP_COMMIT();
            CP_WAIT(1);
        } else {
            CP_WAIT(0);
        }
        __syncthreads();
        compute(buf);
        __syncthreads();
        buf ^= 1;
    }

    // ---- epilogue ----
#pragma unroll
    for (int t = 0; t < 2; t++) {
        const int row0 = bm + wm * 32 + t * 16 + g;
        const int row1 = row0 + 8;
#pragma unroll
        for (int f = 0; f < NFW; f++) {
            const int col = bn + wn * (NT / 2) + f * 8 + tig * 2;
            if (row0 < M) {
                float2 v = {acc[t][f][0], acc[t][f][1]};
                *(float2*)(Cout + (size_t)row0 * NTOT + col) = v;
            }
            if (row1 < M) {
                float2 v = {acc[t][f][2], acc[t][f][3]};
                *(float2*)(Cout + (size_t)row1 * NTOT + col) = v;
            }
        }
    }
}

__global__ void __launch_bounds__(256, 2)
k_gemm1_mma(const float* __restrict__ x) {
    gemm_mma_body<HDIM, 128, IN_C, true>(x, nullptr, nullptr, g_w1t_hi, g_w1t_lo, g_h1, N_NODES);
}
__global__ void __launch_bounds__(256, 2)
k_gemm2_mma() {
    gemm_mma_body<H2DIM, 80, HDIM, false>(nullptr, g_a1_hi, g_a1_lo, g_w2t_hi, g_w2t_lo, g_h2, N_NODES);
}

// ---------------------------------------------------------------------------
// Attention: one warp per destination node, online segment-softmax.
// ---------------------------------------------------------------------------
template <int CTOT, int VPL, bool FINAL>
__device__ __forceinline__ void attn_body(const float* __restrict__ h,
                                          const float* __restrict__ bias,
                                          float* __restrict__ out) {
    int gw   = (blockIdx.x * blockDim.x + threadIdx.x) >> 5;
    int lane = threadIdx.x & 31;
    if (gw >= N_NODES) return;

    float xi[VPL];
    if (VPL == 8) {
        const float4* p = (const float4*)(h + (size_t)gw * CTOT + lane * 8);
        float4 a = p[0], b = p[1];
        xi[0] = a.x; xi[1] = a.y; xi[2] = a.z; xi[3] = a.w;
        xi[4] = b.x; xi[5] = b.y; xi[6] = b.z; xi[7] = b.w;
    } else {
        const float* ib = h + (size_t)gw * CTOT + lane * VPL;
#pragma unroll
        for (int k = 0; k < VPL; k++) xi[k] = ib[k];
    }

    float m = -1e30f, s = 0.f;
    float acc[VPL];
#pragma unroll
    for (int k = 0; k < VPL; k++) acc[k] = 0.f;

    int e0 = g_rowptr[gw], e1 = g_rowptr[gw + 1];
    for (int e = e0; e < e1; e++) {
        int src = g_csrsrc[e];
        float xj[VPL];
        if (VPL == 8) {
            const float4* p = (const float4*)(h + (size_t)src * CTOT + lane * 8);
            float4 a = p[0], b = p[1];
            xj[0] = a.x; xj[1] = a.y; xj[2] = a.z; xj[3] = a.w;
            xj[4] = b.x; xj[5] = b.y; xj[6] = b.z; xj[7] = b.w;
        } else {
            const float* jb = h + (size_t)src * CTOT + lane * VPL;
#pragma unroll
            for (int k = 0; k < VPL; k++) xj[k] = jb[k];
        }
        float d = 0.f;
#pragma unroll
        for (int k = 0; k < VPL; k++) d = fmaf(xi[k], xj[k], d);
        d += __shfl_xor_sync(0xffffffffu, d, 1);
        d += __shfl_xor_sync(0xffffffffu, d, 2);
        d += __shfl_xor_sync(0xffffffffu, d, 4);
        float a = d > 0.f ? d : 0.2f * d;
        float mn = fmaxf(m, a);
        float corr = __expf(m - mn);
        float wgt = __expf(a - mn);
        s = s * corr + wgt;
#pragma unroll
        for (int k = 0; k < VPL; k++) acc[k] = fmaf(acc[k], corr, wgt * xj[k]);
        m = mn;
    }
    float inv = 1.f / (s + 1e-16f);

    if (!FINAL) {
#pragma unroll
        for (int k = 0; k < VPL; k++) {
            float v = acc[k] * inv + bias[lane * VPL + k];
            v = v > 0.f ? v : expm1f(v);
            size_t idx = (size_t)gw * CTOT + lane * VPL + k;
            __nv_bfloat16 hh = __float2bfloat16(v);
            g_a1_hi[idx] = hh;
            g_a1_lo[idx] = __float2bfloat16(v - __bfloat162float(hh));
        }
    } else {
        float r[VPL];
#pragma unroll
        for (int k = 0; k < VPL; k++) r[k] = acc[k] * inv;
#pragma unroll
        for (int k = 0; k < VPL; k++) r[k] += __shfl_down_sync(0xffffffffu, r[k], 16);
#pragma unroll
        for (int k = 0; k < VPL; k++) r[k] += __shfl_down_sync(0xffffffffu, r[k], 8);
        float v[VPL];
        float mx = -1e30f;
        if (lane < 8) {
#pragma unroll
            for (int k = 0; k < VPL; k++) {
                v[k] = 0.25f * r[k] + bias[lane * VPL + k];
                mx = fmaxf(mx, v[k]);
            }
        }
        mx = fmaxf(mx, __shfl_xor_sync(0xffffffffu, mx, 1));
        mx = fmaxf(mx, __shfl_xor_sync(0xffffffffu, mx, 2));
        mx = fmaxf(mx, __shfl_xor_sync(0xffffffffu, mx, 4));
        float se = 0.f;
        if (lane < 8) {
#pragma unroll
            for (int k = 0; k < VPL; k++) se += __expf(v[k] - mx);
        }
        se += __shfl_xor_sync(0xffffffffu, se, 1);
        se += __shfl_xor_sync(0xffffffffu, se, 2);
        se += __shfl_xor_sync(0xffffffffu, se, 4);
        float lse = logf(se) + mx;
        if (lane < 8) {
#pragma unroll
            for (int k = 0; k < VPL; k++)
                out[(size_t)gw * OUT_C + lane * VPL + k] = v[k] - lse;
        }
    }
}

__global__ void k_attn1(const float* __restrict__ b1) {
    attn_body<HDIM, 8, false>(g_h1, b1, nullptr);
}
__global__ void k_attn2(const float* __restrict__ b2, float* __restrict__ out) {
    attn_body<H2DIM, 5, true>(g_h2, b2, out);
}

// ---------------------------------------------------------------------------
// Launch (gemm1 kept as 4th launch for the ncu capture window)
// ---------------------------------------------------------------------------
extern "C" void kernel_launch(void* const* d_in, const int* in_sizes, int n_in,
                              void* d_out, int out_size) {
    const float* x  = (const float*)d_in[0];
    const int*   ei = (const int*)d_in[1];
    const float* W1 = (const float*)d_in[2];
    const float* b1 = (const float*)d_in[3];
    const float* W2 = (const float*)d_in[4];
    const float* b2 = (const float*)d_in[5];
    float* out = (float*)d_out;
    int E = in_sizes[1] / 2;

    const int SMEM1 = 2 * (16384 + 128 * 160);   // 73728 (x2 CTAs = 147KB/SM)
    const int SMEM2 = 2 * (20480 + 80 * 160);    // 66560 (x2 CTAs = 133KB/SM)
    cudaFuncSetAttribute(k_gemm1_mma, cudaFuncAttributeMaxDynamicSharedMemorySize, SMEM1);
    cudaFuncSetAttribute(k_gemm2_mma, cudaFuncAttributeMaxDynamicSharedMemorySize, SMEM2);

    // 1-3: prep + init + hist (all independent of gemm1)
    k_prep_w<<<(IN_C * HDIM + HDIM * H2DIM + 255) / 256, 256>>>(W1, W2);
    k_init_cnt<<<(N_NODES + 255) / 256, 256>>>(out, out_size);
    k_hist<<<(E + 255) / 256, 256>>>(ei, E);

    // 4: GEMM1 (profiled launch) — reads x directly, splits in-kernel
    k_gemm1_mma<<<dim3(2, MBLK), 256, SMEM1>>>(x);

    // 5-6: finish CSR
    k_scan<<<1, 1024>>>(N_NODES);
    k_scatter<<<(E + N_NODES + 255) / 256, 256>>>(ei, E);

    // 7-9: attention + layer 2
    k_attn1<<<(N_NODES + 7) / 8, 256>>>(b1);
    k_gemm2_mma<<<dim3(2, MBLK), 256, SMEM2>>>();
    k_attn2<<<(N_NODES + 7) / 8, 256>>>(b2, out);
}

// round 12
// speedup vs baseline: 3.3775x; 1.0725x over previous
#include <cuda_runtime.h>
#include <cuda_bf16.h>
#include <math.h>
#include <stdint.h>

// Problem constants
#define N_NODES 50000
#define IN_C    512
#define HDIM    256   // H*HID
#define H2DIM   160   // H*OUT_C
#define OUT_C   40
#define MAXE    400000
#define MBLK    391   // ceil(50000/128)

// ---------------------------------------------------------------------------
// Scratch (static device globals)
// ---------------------------------------------------------------------------
__device__ float g_h1[(size_t)N_NODES * HDIM];
__device__ float g_h2[(size_t)N_NODES * H2DIM];
__device__ __align__(16) __nv_bfloat16 g_a1_hi[(size_t)N_NODES * HDIM];
__device__ __align__(16) __nv_bfloat16 g_a1_lo[(size_t)N_NODES * HDIM];
__device__ __align__(16) __nv_bfloat16 g_w1t_hi[(size_t)HDIM * IN_C];   // [n][k]
__device__ __align__(16) __nv_bfloat16 g_w1t_lo[(size_t)HDIM * IN_C];
__device__ __align__(16) __nv_bfloat16 g_w2t_hi[(size_t)H2DIM * HDIM];  // [n][k]
__device__ __align__(16) __nv_bfloat16 g_w2t_lo[(size_t)H2DIM * HDIM];
__device__ int g_cnt[N_NODES];
__device__ int g_rowptr[N_NODES + 1];
__device__ int g_wptr[N_NODES];
__device__ int g_csrsrc[MAXE + N_NODES];

// ---------------------------------------------------------------------------
// mma.sync bf16 + ldmatrix + cp.async helpers (family-common ISA)
// ---------------------------------------------------------------------------
__device__ __forceinline__ void mma_bf16(float* d, const uint32_t* a, const uint32_t* b) {
    asm volatile(
        "mma.sync.aligned.m16n8k16.row.col.f32.bf16.bf16.f32 "
        "{%0,%1,%2,%3}, {%4,%5,%6,%7}, {%8,%9}, {%0,%1,%2,%3};"
        : "+f"(d[0]), "+f"(d[1]), "+f"(d[2]), "+f"(d[3])
        : "r"(a[0]), "r"(a[1]), "r"(a[2]), "r"(a[3]), "r"(b[0]), "r"(b[1]));
}
__device__ __forceinline__ void ldsm_x4(uint32_t* r, uint32_t addr) {
    asm volatile("ldmatrix.sync.aligned.m8n8.x4.shared.b16 {%0,%1,%2,%3}, [%4];"
        : "=r"(r[0]), "=r"(r[1]), "=r"(r[2]), "=r"(r[3]) : "r"(addr));
}
__device__ __forceinline__ void ldsm_x2(uint32_t* r, uint32_t addr) {
    asm volatile("ldmatrix.sync.aligned.m8n8.x2.shared.b16 {%0,%1}, [%2];"
        : "=r"(r[0]), "=r"(r[1]) : "r"(addr));
}
__device__ __forceinline__ uint32_t smem_u32(const void* p) {
    uint32_t a;
    asm("{ .reg .u64 t; cvta.to.shared.u64 t, %1; cvt.u32.u64 %0, t; }" : "=r"(a) : "l"(p));
    return a;
}
#define CP_ASYNC16(dst, src) \
    asm volatile("cp.async.cg.shared.global [%0], [%1], 16;" :: "r"(dst), "l"(src))
#define CP_COMMIT()  asm volatile("cp.async.commit_group;" ::: "memory")
#define CP_WAIT(n)   asm volatile("cp.async.wait_group %0;" :: "n"(n) : "memory")

// Pack 2 fp32 -> bf16x2 reg (lo element in low 16 bits)
__device__ __forceinline__ uint32_t cvt_bf16x2(float hi_elem, float lo_elem) {
    uint32_t r;
    asm("cvt.rn.bf16x2.f32 %0, %1, %2;" : "=r"(r) : "f"(hi_elem), "f"(lo_elem));
    return r;
}

// ---------------------------------------------------------------------------
// Fused weight prep: transpose + bf16 split for W1 and W2 in one launch.
// ---------------------------------------------------------------------------
__global__ void k_prep_w(const float* __restrict__ W1, const float* __restrict__ W2) {
    int idx = blockIdx.x * blockDim.x + threadIdx.x;
    const int N1 = IN_C * HDIM;
    if (idx < N1) {
        int k = idx / HDIM, n = idx % HDIM;
        float v = W1[idx];
        __nv_bfloat16 h = __float2bfloat16(v);
        g_w1t_hi[(size_t)n * IN_C + k] = h;
        g_w1t_lo[(size_t)n * IN_C + k] = __float2bfloat16(v - __bfloat162float(h));
    } else if (idx < N1 + HDIM * H2DIM) {
        int j = idx - N1;
        int k = j / H2DIM, n = j % H2DIM;
        float v = W2[j];
        __nv_bfloat16 h = __float2bfloat16(v);
        g_w2t_hi[(size_t)n * HDIM + k] = h;
        g_w2t_lo[(size_t)n * HDIM + k] = __float2bfloat16(v - __bfloat162float(h));
    }
}

// ---------------------------------------------------------------------------
// CSR construction (+ output tail zeroing folded into init)
// ---------------------------------------------------------------------------
__global__ void k_init_cnt(float* out, int out_size) {
    int i = blockIdx.x * blockDim.x + threadIdx.x;
    if (i < N_NODES) g_cnt[i] = 1;
    if (blockIdx.x == 0) {
        for (int j = N_NODES * OUT_C + threadIdx.x; j < out_size; j += blockDim.x)
            out[j] = 0.f;
    }
}
__global__ void k_hist(const int* __restrict__ ei, int E) {
    int e = blockIdx.x * blockDim.x + threadIdx.x;
    if (e < E) {
        int d = ei[E + e];
        if ((unsigned)d < (unsigned)N_NODES) atomicAdd(&g_cnt[d], 1);
    }
}

// Single-block scan: 1024 threads x 8 elems/iter, shfl warp-scan.
__global__ void k_scan(int n) {
    __shared__ int wsum[32];
    __shared__ int s_carry;
    const int tid = threadIdx.x;
    const int lane = tid & 31, wrp = tid >> 5;
    if (tid == 0) s_carry = 0;
    __syncthreads();
    for (int base = 0; base < n; base += 8192) {
        int i0 = base + tid * 8;
        int v[8], run = 0;
#pragma unroll
        for (int j = 0; j < 8; j++) {
            int vi = (i0 + j < n) ? g_cnt[i0 + j] : 0;
            v[j] = run;
            run += vi;
        }
        int inc = run;
#pragma unroll
        for (int d = 1; d < 32; d <<= 1) {
            int t = __shfl_up_sync(0xffffffffu, inc, d);
            if (lane >= d) inc += t;
        }
        if (lane == 31) wsum[wrp] = inc;
        int carry_in = s_carry;
        __syncthreads();
        if (wrp == 0) {
            int wv = wsum[lane];
            int wi = wv;
#pragma unroll
            for (int d = 1; d < 32; d <<= 1) {
                int t = __shfl_up_sync(0xffffffffu, wi, d);
                if (lane >= d) wi += t;
            }
            wsum[lane] = wi - wv;
            if (lane == 31) s_carry = carry_in + wi;
        }
        __syncthreads();
        int thr_excl = carry_in + wsum[wrp] + (inc - run);
#pragma unroll
        for (int j = 0; j < 8; j++) {
            int i = i0 + j;
            if (i < n) { g_rowptr[i] = thr_excl + v[j]; g_wptr[i] = thr_excl + v[j]; }
        }
        __syncthreads();
    }
    if (tid == 0) g_rowptr[n] = s_carry;
}

__global__ void k_scatter(const int* __restrict__ ei, int E) {
    int e = blockIdx.x * blockDim.x + threadIdx.x;
    int total = E + N_NODES;
    if (e >= total) return;
    int s, d;
    if (e < E) { s = ei[e]; d = ei[E + e]; }
    else       { s = d = e - E; }
    if ((unsigned)d >= (unsigned)N_NODES || (unsigned)s >= (unsigned)N_NODES) return;
    int pos = atomicAdd(&g_wptr[d], 1);
    if ((unsigned)pos < (unsigned)(MAXE + N_NODES)) g_csrsrc[pos] = s;
}

// ---------------------------------------------------------------------------
// Triple-buffered cp.async mma GEMM, 256 threads = 8 warps (4M x 2N),
// two CTAs per SM, ONE barrier per K-chunk.
// CTA computes C[bm:bm+128, bn:bn+NT].
// AFP32: A staged raw fp32 (seg-swizzled), split to bf16 hi/lo at frag load.
// ---------------------------------------------------------------------------
template <int NTOT, int NT, int KTOT, bool AFP32>
__device__ __forceinline__ void gemm_mma_body(const float* __restrict__ Af,
                                              const __nv_bfloat16* __restrict__ Ahi,
                                              const __nv_bfloat16* __restrict__ Alo,
                                              const __nv_bfloat16* __restrict__ Bhi,
                                              const __nv_bfloat16* __restrict__ Blo,
                                              float* __restrict__ Cout, int M) {
    constexpr int BK  = 32;
    constexpr int NCH = KTOT / BK;
    constexpr int NFW = NT / 16;               // n8-frags per warp
    constexpr int AH = 0;                      // bf16-A path offsets
    constexpr int AL = 10240;
    constexpr int BH = AFP32 ? 16384 : 20480;  // fp32 A = 128*128B = 16KB
    constexpr int BL = BH + NT * 80;
    constexpr int STAGE = BH + NT * 160;

    extern __shared__ char sm[];
    const uint32_t smu = smem_u32(sm);

    const int tid  = threadIdx.x;
    const int w    = tid >> 5;
    const int lane = tid & 31;
    const int g    = lane >> 2;
    const int tig  = lane & 3;
    const int wm   = w & 3;                    // 32-row group
    const int wn   = w >> 2;                   // NT/2-col group
    const int bm   = blockIdx.y * 128;
    const int bn   = blockIdx.x * NT;

    const int a_lr   = lane & 15;
    const int a_seg  = lane >> 4;
    const int b_row  = (lane & 7) + ((lane >> 4) << 3);
    const int b_seg  = (lane >> 3) & 1;
    const int b2_row = lane & 7;
    const int b2_seg = (lane >> 3) & 1;

    float acc[2][NFW][4];
#pragma unroll
    for (int t = 0; t < 2; t++)
#pragma unroll
        for (int f = 0; f < NFW; f++)
#pragma unroll
            for (int q = 0; q < 4; q++) acc[t][f][q] = 0.f;

    auto stage = [&](int c, int b) {
        const int kk = c * BK;
        const int total = 1024 + NT * 8;       // 16B transactions
        for (int t = tid; t < total; t += 256) {
            if (t < 1024) {
                if (AFP32) {
                    int r = t >> 3, s = t & 7;
                    int gr = bm + r; if (gr >= M) gr = M - 1;
                    const float* src = Af + (size_t)gr * KTOT + kk + s * 4;
                    uint32_t dst = smu + b * STAGE + r * 128 + ((s ^ (r & 7)) << 4);
                    CP_ASYNC16(dst, src);
                } else {
                    int split = t >> 9, idx = t & 511, r = idx >> 2, seg = idx & 3;
                    int gr = bm + r; if (gr >= M) gr = M - 1;
                    const __nv_bfloat16* src = (split ? Alo : Ahi) + (size_t)gr * KTOT + kk + seg * 8;
                    uint32_t dst = smu + b * STAGE + (split ? AL : AH) + r * 80 + seg * 16;
                    CP_ASYNC16(dst, src);
                }
            } else {
                int j = t - 1024;
                int split = (j >= NT * 4);
                int idx = split ? j - NT * 4 : j;
                int r = idx >> 2, seg = idx & 3;
                const __nv_bfloat16* src = (split ? Blo : Bhi) + (size_t)(bn + r) * KTOT + kk + seg * 8;
                uint32_t dst = smu + b * STAGE + (split ? BL : BH) + r * 80 + seg * 16;
                CP_ASYNC16(dst, src);
            }
        }
    };

    auto compute = [&](int b) {
        const uint32_t pb = smu + b * STAGE;
        const char* pc = sm + (size_t)b * STAGE;
#pragma unroll
        for (int ks = 0; ks < 2; ks++) {
            const int kbyte = ks * 32;
            uint32_t ah[2][4], al[2][4];
            if (AFP32) {
#pragma unroll
                for (int mt = 0; mt < 2; mt++) {
#pragma unroll
                    for (int j = 0; j < 4; j++) {
                        int row = wm * 32 + mt * 16 + g + ((j & 1) << 3);
                        int s = (tig >> 1) + ((j >> 1) << 1) + (ks << 2);
                        int h = tig & 1;
                        const float2 f = *(const float2*)(pc + row * 128 + ((s ^ g) << 4) + (h << 3));
                        uint32_t hi_ = cvt_bf16x2(f.y, f.x);
                        float h0 = __uint_as_float(hi_ << 16);
                        float h1 = __uint_as_float(hi_ & 0xffff0000u);
                        uint32_t lo_ = cvt_bf16x2(f.y - h1, f.x - h0);
                        ah[mt][j] = hi_;
                        al[mt][j] = lo_;
                    }
                }
            } else {
#pragma unroll
                for (int t = 0; t < 2; t++) {
                    uint32_t aoff = (uint32_t)(wm * 32 + t * 16 + a_lr) * 80 + kbyte + a_seg * 16;
                    ldsm_x4(ah[t], pb + AH + aoff);
                    ldsm_x4(al[t], pb + AL + aoff);
                }
            }
            uint32_t bhf[NFW * 2], blf[NFW * 2];
#pragma unroll
            for (int f2 = 0; f2 < NFW / 2; f2++) {
                uint32_t boff = (uint32_t)(wn * (NT / 2) + f2 * 16 + b_row) * 80 + kbyte + b_seg * 16;
                ldsm_x4(&bhf[f2 * 4], pb + BH + boff);
                ldsm_x4(&blf[f2 * 4], pb + BL + boff);
            }
            if (NFW & 1) {
                uint32_t boff = (uint32_t)(wn * (NT / 2) + (NFW - 1) * 8 + b2_row) * 80 + kbyte + b2_seg * 16;
                ldsm_x2(&bhf[(NFW - 1) * 2], pb + BH + boff);
                ldsm_x2(&blf[(NFW - 1) * 2], pb + BL + boff);
            }
#pragma unroll
            for (int f = 0; f < NFW; f++) {
#pragma unroll
                for (int t = 0; t < 2; t++) {
                    mma_bf16(acc[t][f], ah[t], &bhf[f * 2]);
                    mma_bf16(acc[t][f], ah[t], &blf[f * 2]);
                    mma_bf16(acc[t][f], al[t], &bhf[f * 2]);
                }
            }
        }
    };

    // triple-buffered pipeline, one barrier per chunk
    stage(0, 0);
    CP_COMMIT();
    stage(1, 1);
    CP_COMMIT();
    for (int c = 0; c < NCH; c++) {
        if (c < NCH - 1) { CP_WAIT(1); } else { CP_WAIT(0); }
        __syncthreads();   // buf c%3 arrived; all warps done computing (c-1)%3
        if (c + 2 < NCH) {
            stage(c + 2, (c + 2) % 3);   // writes (c+2)%3 — read only at iter c+2
            CP_COMMIT();
        }
        compute(c % 3);
    }

    // ---- epilogue ----
#pragma unroll
    for (int t = 0; t < 2; t++) {
        const int row0 = bm + wm * 32 + t * 16 + g;
        const int row1 = row0 + 8;
#pragma unroll
        for (int f = 0; f < NFW; f++) {
            const int col = bn + wn * (NT / 2) + f * 8 + tig * 2;
            if (row0 < M) {
                float2 v = {acc[t][f][0], acc[t][f][1]};
                *(float2*)(Cout + (size_t)row0 * NTOT + col) = v;
            }
            if (row1 < M) {
                float2 v = {acc[t][f][2], acc[t][f][3]};
                *(float2*)(Cout + (size_t)row1 * NTOT + col) = v;
            }
        }
    }
}

__global__ void __launch_bounds__(256, 2)
k_gemm1_mma(const float* __restrict__ x) {
    gemm_mma_body<HDIM, 128, IN_C, true>(x, nullptr, nullptr, g_w1t_hi, g_w1t_lo, g_h1, N_NODES);
}
__global__ void __launch_bounds__(256, 2)
k_gemm2_mma() {
    gemm_mma_body<H2DIM, 80, HDIM, false>(nullptr, g_a1_hi, g_a1_lo, g_w2t_hi, g_w2t_lo, g_h2, N_NODES);
}

// ---------------------------------------------------------------------------
// Attention: one warp per destination node, online segment-softmax.
// ---------------------------------------------------------------------------
template <int CTOT, int VPL, bool FINAL>
__device__ __forceinline__ void attn_body(const float* __restrict__ h,
                                          const float* __restrict__ bias,
                                          float* __restrict__ out) {
    int gw   = (blockIdx.x * blockDim.x + threadIdx.x) >> 5;
    int lane = threadIdx.x & 31;
    if (gw >= N_NODES) return;

    float xi[VPL];
    if (VPL == 8) {
        const float4* p = (const float4*)(h + (size_t)gw * CTOT + lane * 8);
        float4 a = p[0], b = p[1];
        xi[0] = a.x; xi[1] = a.y; xi[2] = a.z; xi[3] = a.w;
        xi[4] = b.x; xi[5] = b.y; xi[6] = b.z; xi[7] = b.w;
    } else {
        const float* ib = h + (size_t)gw * CTOT + lane * VPL;
#pragma unroll
        for (int k = 0; k < VPL; k++) xi[k] = ib[k];
    }

    float m = -1e30f, s = 0.f;
    float acc[VPL];
#pragma unroll
    for (int k = 0; k < VPL; k++) acc[k] = 0.f;

    int e0 = g_rowptr[gw], e1 = g_rowptr[gw + 1];
    for (int e = e0; e < e1; e++) {
        int src = g_csrsrc[e];
        float xj[VPL];
        if (VPL == 8) {
            const float4* p = (const float4*)(h + (size_t)src * CTOT + lane * 8);
            float4 a = p[0], b = p[1];
            xj[0] = a.x; xj[1] = a.y; xj[2] = a.z; xj[3] = a.w;
            xj[4] = b.x; xj[5] = b.y; xj[6] = b.z; xj[7] = b.w;
        } else {
            const float* jb = h + (size_t)src * CTOT + lane * VPL;
#pragma unroll
            for (int k = 0; k < VPL; k++) xj[k] = jb[k];
        }
        float d = 0.f;
#pragma unroll
        for (int k = 0; k < VPL; k++) d = fmaf(xi[k], xj[k], d);
        d += __shfl_xor_sync(0xffffffffu, d, 1);
        d += __shfl_xor_sync(0xffffffffu, d, 2);
        d += __shfl_xor_sync(0xffffffffu, d, 4);
        float a = d > 0.f ? d : 0.2f * d;
        float mn = fmaxf(m, a);
        float corr = __expf(m - mn);
        float wgt = __expf(a - mn);
        s = s * corr + wgt;
#pragma unroll
        for (int k = 0; k < VPL; k++) acc[k] = fmaf(acc[k], corr, wgt * xj[k]);
        m = mn;
    }
    float inv = 1.f / (s + 1e-16f);

    if (!FINAL) {
#pragma unroll
        for (int k = 0; k < VPL; k++) {
            float v = acc[k] * inv + bias[lane * VPL + k];
            v = v > 0.f ? v : expm1f(v);
            size_t idx = (size_t)gw * CTOT + lane * VPL + k;
            __nv_bfloat16 hh = __float2bfloat16(v);
            g_a1_hi[idx] = hh;
            g_a1_lo[idx] = __float2bfloat16(v - __bfloat162float(hh));
        }
    } else {
        float r[VPL];
#pragma unroll
        for (int k = 0; k < VPL; k++) r[k] = acc[k] * inv;
#pragma unroll
        for (int k = 0; k < VPL; k++) r[k] += __shfl_down_sync(0xffffffffu, r[k], 16);
#pragma unroll
        for (int k = 0; k < VPL; k++) r[k] += __shfl_down_sync(0xffffffffu, r[k], 8);
        float v[VPL];
        float mx = -1e30f;
        if (lane < 8) {
#pragma unroll
            for (int k = 0; k < VPL; k++) {
                v[k] = 0.25f * r[k] + bias[lane * VPL + k];
                mx = fmaxf(mx, v[k]);
            }
        }
        mx = fmaxf(mx, __shfl_xor_sync(0xffffffffu, mx, 1));
        mx = fmaxf(mx, __shfl_xor_sync(0xffffffffu, mx, 2));
        mx = fmaxf(mx, __shfl_xor_sync(0xffffffffu, mx, 4));
        float se = 0.f;
        if (lane < 8) {
#pragma unroll
            for (int k = 0; k < VPL; k++) se += __expf(v[k] - mx);
        }
        se += __shfl_xor_sync(0xffffffffu, se, 1);
        se += __shfl_xor_sync(0xffffffffu, se, 2);
        se += __shfl_xor_sync(0xffffffffu, se, 4);
        float lse = logf(se) + mx;
        if (lane < 8) {
#pragma unroll
            for (int k = 0; k < VPL; k++)
                out[(size_t)gw * OUT_C + lane * VPL + k] = v[k] - lse;
        }
    }
}

__global__ void k_attn1(const float* __restrict__ b1) {
    attn_body<HDIM, 8, false>(g_h1, b1, nullptr);
}
__global__ void k_attn2(const float* __restrict__ b2, float* __restrict__ out) {
    attn_body<H2DIM, 5, true>(g_h2, b2, out);
}

// ---------------------------------------------------------------------------
// Launch: CSR build forked onto a side stream, overlapping gemm1.
// ---------------------------------------------------------------------------
extern "C" void kernel_launch(void* const* d_in, const int* in_sizes, int n_in,
                              void* d_out, int out_size) {
    const float* x  = (const float*)d_in[0];
    const int*   ei = (const int*)d_in[1];
    const float* W1 = (const float*)d_in[2];
    const float* b1 = (const float*)d_in[3];
    const float* W2 = (const float*)d_in[4];
    const float* b2 = (const float*)d_in[5];
    float* out = (float*)d_out;
    int E = in_sizes[1] / 2;

    const int SMEM1 = 3 * (16384 + 128 * 160);   // 110592 (x2 CTAs/SM)
    const int SMEM2 = 3 * (20480 + 80 * 160);    // 99840  (x2 CTAs/SM)
    cudaFuncSetAttribute(k_gemm1_mma, cudaFuncAttributeMaxDynamicSharedMemorySize, SMEM1);
    cudaFuncSetAttribute(k_gemm2_mma, cudaFuncAttributeMaxDynamicSharedMemorySize, SMEM2);

    // One-time host objects (no device memory).
    static cudaStream_t s_side = nullptr;
    static cudaEvent_t  s_fork = nullptr, s_join = nullptr;
    if (s_side == nullptr) {
        cudaStreamCreateWithFlags(&s_side, cudaStreamNonBlocking);
        cudaEventCreateWithFlags(&s_fork, cudaEventDisableTiming);
        cudaEventCreateWithFlags(&s_join, cudaEventDisableTiming);
    }

    // main stream: weight prep (gemm1 dependency)
    k_prep_w<<<(IN_C * HDIM + HDIM * H2DIM + 255) / 256, 256>>>(W1, W2);

    // fork: CSR build on side stream, concurrent with gemm1
    cudaEventRecord(s_fork, 0);
    cudaStreamWaitEvent(s_side, s_fork, 0);
    k_init_cnt<<<(N_NODES + 255) / 256, 256, 0, s_side>>>(out, out_size);
    k_hist<<<(E + 255) / 256, 256, 0, s_side>>>(ei, E);
    k_scan<<<1, 1024, 0, s_side>>>(N_NODES);
    k_scatter<<<(E + N_NODES + 255) / 256, 256, 0, s_side>>>(ei, E);
    cudaEventRecord(s_join, s_side);

    // main stream: gemm1 runs concurrently with the CSR chain
    k_gemm1_mma<<<dim3(2, MBLK), 256, SMEM1>>>(x);

    // join: attn1 needs both gemm1 (main) and CSR (side)
    cudaStreamWaitEvent(0, s_join, 0);
    k_attn1<<<(N_NODES + 7) / 8, 256>>>(b1);
    k_gemm2_mma<<<dim3(2, MBLK), 256, SMEM2>>>();
    k_attn2<<<(N_NODES + 7) / 8, 256>>>(b2, out);
}

// round 13
// speedup vs baseline: 3.5075x; 1.0385x over previous
#include <cuda_runtime.h>
#include <cuda_bf16.h>
#include <math.h>
#include <stdint.h>

// Problem constants
#define N_NODES 50000
#define IN_C    512
#define HDIM    256   // H*HID
#define H2DIM   160   // H*OUT_C
#define OUT_C   40
#define MAXE    400000
#define MBLK    391   // ceil(50000/128)

// ---------------------------------------------------------------------------
// Scratch (static device globals)
// ---------------------------------------------------------------------------
__device__ float g_h1[(size_t)N_NODES * HDIM];
__device__ float g_h2[(size_t)N_NODES * H2DIM];
__device__ __align__(16) __nv_bfloat16 g_a1_hi[(size_t)N_NODES * HDIM];
__device__ __align__(16) __nv_bfloat16 g_a1_lo[(size_t)N_NODES * HDIM];
__device__ __align__(16) __nv_bfloat16 g_w1t_hi[(size_t)HDIM * IN_C];   // [n][k]
__device__ __align__(16) __nv_bfloat16 g_w1t_lo[(size_t)HDIM * IN_C];
__device__ __align__(16) __nv_bfloat16 g_w2t_hi[(size_t)H2DIM * HDIM];  // [n][k]
__device__ __align__(16) __nv_bfloat16 g_w2t_lo[(size_t)H2DIM * HDIM];
__device__ int g_cnt[N_NODES];
__device__ int g_rowptr[N_NODES + 1];
__device__ int g_wptr[N_NODES];
__device__ int g_csrsrc[MAXE + N_NODES];

// ---------------------------------------------------------------------------
// mma.sync bf16 + ldmatrix + cp.async helpers (family-common ISA)
// ---------------------------------------------------------------------------
__device__ __forceinline__ void mma_bf16(float* d, const uint32_t* a, const uint32_t* b) {
    asm volatile(
        "mma.sync.aligned.m16n8k16.row.col.f32.bf16.bf16.f32 "
        "{%0,%1,%2,%3}, {%4,%5,%6,%7}, {%8,%9}, {%0,%1,%2,%3};"
        : "+f"(d[0]), "+f"(d[1]), "+f"(d[2]), "+f"(d[3])
        : "r"(a[0]), "r"(a[1]), "r"(a[2]), "r"(a[3]), "r"(b[0]), "r"(b[1]));
}
__device__ __forceinline__ void ldsm_x4(uint32_t* r, uint32_t addr) {
    asm volatile("ldmatrix.sync.aligned.m8n8.x4.shared.b16 {%0,%1,%2,%3}, [%4];"
        : "=r"(r[0]), "=r"(r[1]), "=r"(r[2]), "=r"(r[3]) : "r"(addr));
}
__device__ __forceinline__ void ldsm_x2(uint32_t* r, uint32_t addr) {
    asm volatile("ldmatrix.sync.aligned.m8n8.x2.shared.b16 {%0,%1}, [%2];"
        : "=r"(r[0]), "=r"(r[1]) : "r"(addr));
}
__device__ __forceinline__ uint32_t smem_u32(const void* p) {
    uint32_t a;
    asm("{ .reg .u64 t; cvta.to.shared.u64 t, %1; cvt.u32.u64 %0, t; }" : "=r"(a) : "l"(p));
    return a;
}
#define CP_ASYNC16(dst, src) \
    asm volatile("cp.async.cg.shared.global [%0], [%1], 16;" :: "r"(dst), "l"(src))
#define CP_COMMIT()  asm volatile("cp.async.commit_group;" ::: "memory")
#define CP_WAIT(n)   asm volatile("cp.async.wait_group %0;" :: "n"(n) : "memory")

// Pack 2 fp32 -> bf16x2 reg (lo element in low 16 bits)
__device__ __forceinline__ uint32_t cvt_bf16x2(float hi_elem, float lo_elem) {
    uint32_t r;
    asm("cvt.rn.bf16x2.f32 %0, %1, %2;" : "=r"(r) : "f"(hi_elem), "f"(lo_elem));
    return r;
}

// ---------------------------------------------------------------------------
// Fused weight prep: transpose + bf16 split for W1 and W2 in one launch.
// ---------------------------------------------------------------------------
__global__ void k_prep_w(const float* __restrict__ W1, const float* __restrict__ W2) {
    int idx = blockIdx.x * blockDim.x + threadIdx.x;
    const int N1 = IN_C * HDIM;
    if (idx < N1) {
        int k = idx / HDIM, n = idx % HDIM;
        float v = W1[idx];
        __nv_bfloat16 h = __float2bfloat16(v);
        g_w1t_hi[(size_t)n * IN_C + k] = h;
        g_w1t_lo[(size_t)n * IN_C + k] = __float2bfloat16(v - __bfloat162float(h));
    } else if (idx < N1 + HDIM * H2DIM) {
        int j = idx - N1;
        int k = j / H2DIM, n = j % H2DIM;
        float v = W2[j];
        __nv_bfloat16 h = __float2bfloat16(v);
        g_w2t_hi[(size_t)n * HDIM + k] = h;
        g_w2t_lo[(size_t)n * HDIM + k] = __float2bfloat16(v - __bfloat162float(h));
    }
}

// ---------------------------------------------------------------------------
// CSR construction (+ output tail zeroing folded into init)
// ---------------------------------------------------------------------------
__global__ void k_init_cnt(float* out, int out_size) {
    int i = blockIdx.x * blockDim.x + threadIdx.x;
    if (i < N_NODES) g_cnt[i] = 1;
    if (blockIdx.x == 0) {
        for (int j = N_NODES * OUT_C + threadIdx.x; j < out_size; j += blockDim.x)
            out[j] = 0.f;
    }
}
__global__ void k_hist(const int* __restrict__ ei, int E) {
    int e = blockIdx.x * blockDim.x + threadIdx.x;
    if (e < E) {
        int d = ei[E + e];
        if ((unsigned)d < (unsigned)N_NODES) atomicAdd(&g_cnt[d], 1);
    }
}

// Single-block scan: 1024 threads x 8 elems/iter, shfl warp-scan.
__global__ void k_scan(int n) {
    __shared__ int wsum[32];
    __shared__ int s_carry;
    const int tid = threadIdx.x;
    const int lane = tid & 31, wrp = tid >> 5;
    if (tid == 0) s_carry = 0;
    __syncthreads();
    for (int base = 0; base < n; base += 8192) {
        int i0 = base + tid * 8;
        int v[8], run = 0;
#pragma unroll
        for (int j = 0; j < 8; j++) {
            int vi = (i0 + j < n) ? g_cnt[i0 + j] : 0;
            v[j] = run;
            run += vi;
        }
        int inc = run;
#pragma unroll
        for (int d = 1; d < 32; d <<= 1) {
            int t = __shfl_up_sync(0xffffffffu, inc, d);
            if (lane >= d) inc += t;
        }
        if (lane == 31) wsum[wrp] = inc;
        int carry_in = s_carry;
        __syncthreads();
        if (wrp == 0) {
            int wv = wsum[lane];
            int wi = wv;
#pragma unroll
            for (int d = 1; d < 32; d <<= 1) {
                int t = __shfl_up_sync(0xffffffffu, wi, d);
                if (lane >= d) wi += t;
            }
            wsum[lane] = wi - wv;
            if (lane == 31) s_carry = carry_in + wi;
        }
        __syncthreads();
        int thr_excl = carry_in + wsum[wrp] + (inc - run);
#pragma unroll
        for (int j = 0; j < 8; j++) {
            int i = i0 + j;
            if (i < n) { g_rowptr[i] = thr_excl + v[j]; g_wptr[i] = thr_excl + v[j]; }
        }
        __syncthreads();
    }
    if (tid == 0) g_rowptr[n] = s_carry;
}

__global__ void k_scatter(const int* __restrict__ ei, int E) {
    int e = blockIdx.x * blockDim.x + threadIdx.x;
    int total = E + N_NODES;
    if (e >= total) return;
    int s, d;
    if (e < E) { s = ei[e]; d = ei[E + e]; }
    else       { s = d = e - E; }
    if ((unsigned)d >= (unsigned)N_NODES || (unsigned)s >= (unsigned)N_NODES) return;
    int pos = atomicAdd(&g_wptr[d], 1);
    if ((unsigned)pos < (unsigned)(MAXE + N_NODES)) g_csrsrc[pos] = s;
}

// ---------------------------------------------------------------------------
// Triple-buffered cp.async mma GEMM, 256 threads = 8 warps (4M x 2N),
// two CTAs per SM, ONE barrier per K-chunk.
// AFP32: A staged raw fp32 (seg-swizzled), split to bf16 hi/lo at frag load.
// ---------------------------------------------------------------------------
template <int NTOT, int NT, int KTOT, bool AFP32>
__device__ __forceinline__ void gemm_mma_body(const float* __restrict__ Af,
                                              const __nv_bfloat16* __restrict__ Ahi,
                                              const __nv_bfloat16* __restrict__ Alo,
                                              const __nv_bfloat16* __restrict__ Bhi,
                                              const __nv_bfloat16* __restrict__ Blo,
                                              float* __restrict__ Cout, int M) {
    constexpr int BK  = 32;
    constexpr int NCH = KTOT / BK;
    constexpr int NFW = NT / 16;               // n8-frags per warp
    constexpr int AH = 0;
    constexpr int AL = 10240;
    constexpr int BH = AFP32 ? 16384 : 20480;
    constexpr int BL = BH + NT * 80;
    constexpr int STAGE = BH + NT * 160;

    extern __shared__ char sm[];
    const uint32_t smu = smem_u32(sm);

    const int tid  = threadIdx.x;
    const int w    = tid >> 5;
    const int lane = tid & 31;
    const int g    = lane >> 2;
    const int tig  = lane & 3;
    const int wm   = w & 3;
    const int wn   = w >> 2;
    const int bm   = blockIdx.y * 128;
    const int bn   = blockIdx.x * NT;

    const int a_lr   = lane & 15;
    const int a_seg  = lane >> 4;
    const int b_row  = (lane & 7) + ((lane >> 4) << 3);
    const int b_seg  = (lane >> 3) & 1;
    const int b2_row = lane & 7;
    const int b2_seg = (lane >> 3) & 1;

    float acc[2][NFW][4];
#pragma unroll
    for (int t = 0; t < 2; t++)
#pragma unroll
        for (int f = 0; f < NFW; f++)
#pragma unroll
            for (int q = 0; q < 4; q++) acc[t][f][q] = 0.f;

    auto stage = [&](int c, int b) {
        const int kk = c * BK;
        const int total = 1024 + NT * 8;
        for (int t = tid; t < total; t += 256) {
            if (t < 1024) {
                if (AFP32) {
                    int r = t >> 3, s = t & 7;
                    int gr = bm + r; if (gr >= M) gr = M - 1;
                    const float* src = Af + (size_t)gr * KTOT + kk + s * 4;
                    uint32_t dst = smu + b * STAGE + r * 128 + ((s ^ (r & 7)) << 4);
                    CP_ASYNC16(dst, src);
                } else {
                    int split = t >> 9, idx = t & 511, r = idx >> 2, seg = idx & 3;
                    int gr = bm + r; if (gr >= M) gr = M - 1;
                    const __nv_bfloat16* src = (split ? Alo : Ahi) + (size_t)gr * KTOT + kk + seg * 8;
                    uint32_t dst = smu + b * STAGE + (split ? AL : AH) + r * 80 + seg * 16;
                    CP_ASYNC16(dst, src);
                }
            } else {
                int j = t - 1024;
                int split = (j >= NT * 4);
                int idx = split ? j - NT * 4 : j;
                int r = idx >> 2, seg = idx & 3;
                const __nv_bfloat16* src = (split ? Blo : Bhi) + (size_t)(bn + r) * KTOT + kk + seg * 8;
                uint32_t dst = smu + b * STAGE + (split ? BL : BH) + r * 80 + seg * 16;
                CP_ASYNC16(dst, src);
            }
        }
    };

    auto compute = [&](int b) {
        const uint32_t pb = smu + b * STAGE;
        const char* pc = sm + (size_t)b * STAGE;
#pragma unroll
        for (int ks = 0; ks < 2; ks++) {
            const int kbyte = ks * 32;
            uint32_t ah[2][4], al[2][4];
            if (AFP32) {
#pragma unroll
                for (int mt = 0; mt < 2; mt++) {
#pragma unroll
                    for (int j = 0; j < 4; j++) {
                        int row = wm * 32 + mt * 16 + g + ((j & 1) << 3);
                        int s = (tig >> 1) + ((j >> 1) << 1) + (ks << 2);
                        int h = tig & 1;
                        const float2 f = *(const float2*)(pc + row * 128 + ((s ^ g) << 4) + (h << 3));
                        uint32_t hi_ = cvt_bf16x2(f.y, f.x);
                        float h0 = __uint_as_float(hi_ << 16);
                        float h1 = __uint_as_float(hi_ & 0xffff0000u);
                        uint32_t lo_ = cvt_bf16x2(f.y - h1, f.x - h0);
                        ah[mt][j] = hi_;
                        al[mt][j] = lo_;
                    }
                }
            } else {
#pragma unroll
                for (int t = 0; t < 2; t++) {
                    uint32_t aoff = (uint32_t)(wm * 32 + t * 16 + a_lr) * 80 + kbyte + a_seg * 16;
                    ldsm_x4(ah[t], pb + AH + aoff);
                    ldsm_x4(al[t], pb + AL + aoff);
                }
            }
            uint32_t bhf[NFW * 2], blf[NFW * 2];
#pragma unroll
            for (int f2 = 0; f2 < NFW / 2; f2++) {
                uint32_t boff = (uint32_t)(wn * (NT / 2) + f2 * 16 + b_row) * 80 + kbyte + b_seg * 16;
                ldsm_x4(&bhf[f2 * 4], pb + BH + boff);
                ldsm_x4(&blf[f2 * 4], pb + BL + boff);
            }
            if (NFW & 1) {
                uint32_t boff = (uint32_t)(wn * (NT / 2) + (NFW - 1) * 8 + b2_row) * 80 + kbyte + b2_seg * 16;
                ldsm_x2(&bhf[(NFW - 1) * 2], pb + BH + boff);
                ldsm_x2(&blf[(NFW - 1) * 2], pb + BL + boff);
            }
#pragma unroll
            for (int f = 0; f < NFW; f++) {
#pragma unroll
                for (int t = 0; t < 2; t++) {
                    mma_bf16(acc[t][f], ah[t], &bhf[f * 2]);
                    mma_bf16(acc[t][f], ah[t], &blf[f * 2]);
                    mma_bf16(acc[t][f], al[t], &bhf[f * 2]);
                }
            }
        }
    };

    stage(0, 0);
    CP_COMMIT();
    stage(1, 1);
    CP_COMMIT();
    for (int c = 0; c < NCH; c++) {
        if (c < NCH - 1) { CP_WAIT(1); } else { CP_WAIT(0); }
        __syncthreads();
        if (c + 2 < NCH) {
            stage(c + 2, (c + 2) % 3);
            CP_COMMIT();
        }
        compute(c % 3);
    }

    // ---- epilogue ----
#pragma unroll
    for (int t = 0; t < 2; t++) {
        const int row0 = bm + wm * 32 + t * 16 + g;
        const int row1 = row0 + 8;
#pragma unroll
        for (int f = 0; f < NFW; f++) {
            const int col = bn + wn * (NT / 2) + f * 8 + tig * 2;
            if (row0 < M) {
                float2 v = {acc[t][f][0], acc[t][f][1]};
                *(float2*)(Cout + (size_t)row0 * NTOT + col) = v;
            }
            if (row1 < M) {
                float2 v = {acc[t][f][2], acc[t][f][3]};
                *(float2*)(Cout + (size_t)row1 * NTOT + col) = v;
            }
        }
    }
}

__global__ void __launch_bounds__(256, 2)
k_gemm1_mma(const float* __restrict__ x) {
    gemm_mma_body<HDIM, 128, IN_C, true>(x, nullptr, nullptr, g_w1t_hi, g_w1t_lo, g_h1, N_NODES);
}
__global__ void __launch_bounds__(256, 2)
k_gemm2_mma() {
    gemm_mma_body<H2DIM, 80, HDIM, false>(nullptr, g_a1_hi, g_a1_lo, g_w2t_hi, g_w2t_lo, g_h2, N_NODES);
}

// ---------------------------------------------------------------------------
// Attention: one warp per destination node, online segment-softmax.
// Edge loop processed in PAIRS: both gathers issued before any use (MLP 2->4)
// to hide L2 latency; softmax updates stay sequential (numerics unchanged).
// ---------------------------------------------------------------------------
template <int CTOT, int VPL>
__device__ __forceinline__ void attn_load(const float* __restrict__ h,
                                          int node, int lane, float* xj) {
    if (VPL == 8) {
        const float4* p = (const float4*)(h + (size_t)node * CTOT + lane * 8);
        float4 a = p[0], b = p[1];
        xj[0] = a.x; xj[1] = a.y; xj[2] = a.z; xj[3] = a.w;
        xj[4] = b.x; xj[5] = b.y; xj[6] = b.z; xj[7] = b.w;
    } else {
        const float* jb = h + (size_t)node * CTOT + lane * VPL;
#pragma unroll
        for (int k = 0; k < VPL; k++) xj[k] = jb[k];
    }
}

template <int CTOT, int VPL, bool FINAL>
__device__ __forceinline__ void attn_body(const float* __restrict__ h,
                                          const float* __restrict__ bias,
                                          float* __restrict__ out) {
    int gw   = (blockIdx.x * blockDim.x + threadIdx.x) >> 5;
    int lane = threadIdx.x & 31;
    if (gw >= N_NODES) return;

    float xi[VPL];
    attn_load<CTOT, VPL>(h, gw, lane, xi);

    float m = -1e30f, s = 0.f;
    float acc[VPL];
#pragma unroll
    for (int k = 0; k < VPL; k++) acc[k] = 0.f;

    const int e0 = g_rowptr[gw], e1 = g_rowptr[gw + 1];
    int e = e0;
    for (; e + 1 < e1; e += 2) {
        // issue both index loads, then both gathers, before any consumption
        int s0 = g_csrsrc[e];
        int s1 = g_csrsrc[e + 1];
        float xj0[VPL], xj1[VPL];
        attn_load<CTOT, VPL>(h, s0, lane, xj0);
        attn_load<CTOT, VPL>(h, s1, lane, xj1);
        // interleaved dot reductions
        float d0 = 0.f, d1 = 0.f;
#pragma unroll
        for (int k = 0; k < VPL; k++) { d0 = fmaf(xi[k], xj0[k], d0); d1 = fmaf(xi[k], xj1[k], d1); }
        d0 += __shfl_xor_sync(0xffffffffu, d0, 1);
        d1 += __shfl_xor_sync(0xffffffffu, d1, 1);
        d0 += __shfl_xor_sync(0xffffffffu, d0, 2);
        d1 += __shfl_xor_sync(0xffffffffu, d1, 2);
        d0 += __shfl_xor_sync(0xffffffffu, d0, 4);
        d1 += __shfl_xor_sync(0xffffffffu, d1, 4);
        // sequential softmax updates (same order as scalar loop)
        {
            float a = d0 > 0.f ? d0 : 0.2f * d0;
            float mn = fmaxf(m, a);
            float corr = __expf(m - mn);
            float wgt = __expf(a - mn);
            s = s * corr + wgt;
#pragma unroll
            for (int k = 0; k < VPL; k++) acc[k] = fmaf(acc[k], corr, wgt * xj0[k]);
            m = mn;
        }
        {
            float a = d1 > 0.f ? d1 : 0.2f * d1;
            float mn = fmaxf(m, a);
            float corr = __expf(m - mn);
            float wgt = __expf(a - mn);
            s = s * corr + wgt;
#pragma unroll
            for (int k = 0; k < VPL; k++) acc[k] = fmaf(acc[k], corr, wgt * xj1[k]);
            m = mn;
        }
    }
    if (e < e1) {
        int s0 = g_csrsrc[e];
        float xj0[VPL];
        attn_load<CTOT, VPL>(h, s0, lane, xj0);
        float d0 = 0.f;
#pragma unroll
        for (int k = 0; k < VPL; k++) d0 = fmaf(xi[k], xj0[k], d0);
        d0 += __shfl_xor_sync(0xffffffffu, d0, 1);
        d0 += __shfl_xor_sync(0xffffffffu, d0, 2);
        d0 += __shfl_xor_sync(0xffffffffu, d0, 4);
        float a = d0 > 0.f ? d0 : 0.2f * d0;
        float mn = fmaxf(m, a);
        float corr = __expf(m - mn);
        float wgt = __expf(a - mn);
        s = s * corr + wgt;
#pragma unroll
        for (int k = 0; k < VPL; k++) acc[k] = fmaf(acc[k], corr, wgt * xj0[k]);
        m = mn;
    }
    float inv = 1.f / (s + 1e-16f);

    if (!FINAL) {
#pragma unroll
        for (int k = 0; k < VPL; k++) {
            float v = acc[k] * inv + bias[lane * VPL + k];
            v = v > 0.f ? v : expm1f(v);
            size_t idx = (size_t)gw * CTOT + lane * VPL + k;
            __nv_bfloat16 hh = __float2bfloat16(v);
            g_a1_hi[idx] = hh;
            g_a1_lo[idx] = __float2bfloat16(v - __bfloat162float(hh));
        }
    } else {
        float r[VPL];
#pragma unroll
        for (int k = 0; k < VPL; k++) r[k] = acc[k] * inv;
#pragma unroll
        for (int k = 0; k < VPL; k++) r[k] += __shfl_down_sync(0xffffffffu, r[k], 16);
#pragma unroll
        for (int k = 0; k < VPL; k++) r[k] += __shfl_down_sync(0xffffffffu, r[k], 8);
        float v[VPL];
        float mx = -1e30f;
        if (lane < 8) {
#pragma unroll
            for (int k = 0; k < VPL; k++) {
                v[k] = 0.25f * r[k] + bias[lane * VPL + k];
                mx = fmaxf(mx, v[k]);
            }
        }
        mx = fmaxf(mx, __shfl_xor_sync(0xffffffffu, mx, 1));
        mx = fmaxf(mx, __shfl_xor_sync(0xffffffffu, mx, 2));
        mx = fmaxf(mx, __shfl_xor_sync(0xffffffffu, mx, 4));
        float se = 0.f;
        if (lane < 8) {
#pragma unroll
            for (int k = 0; k < VPL; k++) se += __expf(v[k] - mx);
        }
        se += __shfl_xor_sync(0xffffffffu, se, 1);
        se += __shfl_xor_sync(0xffffffffu, se, 2);
        se += __shfl_xor_sync(0xffffffffu, se, 4);
        float lse = logf(se) + mx;
        if (lane < 8) {
#pragma unroll
            for (int k = 0; k < VPL; k++)
                out[(size_t)gw * OUT_C + lane * VPL + k] = v[k] - lse;
        }
    }
}

__global__ void k_attn1(const float* __restrict__ b1) {
    attn_body<HDIM, 8, false>(g_h1, b1, nullptr);
}
__global__ void k_attn2(const float* __restrict__ b2, float* __restrict__ out) {
    attn_body<H2DIM, 5, true>(g_h2, b2, out);
}

// ---------------------------------------------------------------------------
// Launch: CSR build forked onto a side stream, overlapping gemm1.
// ---------------------------------------------------------------------------
extern "C" void kernel_launch(void* const* d_in, const int* in_sizes, int n_in,
                              void* d_out, int out_size) {
    const float* x  = (const float*)d_in[0];
    const int*   ei = (const int*)d_in[1];
    const float* W1 = (const float*)d_in[2];
    const float* b1 = (const float*)d_in[3];
    const float* W2 = (const float*)d_in[4];
    const float* b2 = (const float*)d_in[5];
    float* out = (float*)d_out;
    int E = in_sizes[1] / 2;

    const int SMEM1 = 3 * (16384 + 128 * 160);   // 110592 (x2 CTAs/SM)
    const int SMEM2 = 3 * (20480 + 80 * 160);    // 99840  (x2 CTAs/SM)
    cudaFuncSetAttribute(k_gemm1_mma, cudaFuncAttributeMaxDynamicSharedMemorySize, SMEM1);
    cudaFuncSetAttribute(k_gemm2_mma, cudaFuncAttributeMaxDynamicSharedMemorySize, SMEM2);

    // One-time host objects (no device memory).
    static cudaStream_t s_side = nullptr;
    static cudaEvent_t  s_fork = nullptr, s_join = nullptr;
    if (s_side == nullptr) {
        cudaStreamCreateWithFlags(&s_side, cudaStreamNonBlocking);
        cudaEventCreateWithFlags(&s_fork, cudaEventDisableTiming);
        cudaEventCreateWithFlags(&s_join, cudaEventDisableTiming);
    }

    // main stream: weight prep (gemm1 dependency)
    k_prep_w<<<(IN_C * HDIM + HDIM * H2DIM + 255) / 256, 256>>>(W1, W2);

    // fork: CSR build on side stream, concurrent with gemm1
    cudaEventRecord(s_fork, 0);
    cudaStreamWaitEvent(s_side, s_fork, 0);
    k_init_cnt<<<(N_NODES + 255) / 256, 256, 0, s_side>>>(out, out_size);
    k_hist<<<(E + 255) / 256, 256, 0, s_side>>>(ei, E);
    k_scan<<<1, 1024, 0, s_side>>>(N_NODES);
    k_scatter<<<(E + N_NODES + 255) / 256, 256, 0, s_side>>>(ei, E);
    cudaEventRecord(s_join, s_side);

    // main stream: gemm1 runs concurrently with the CSR chain
    k_gemm1_mma<<<dim3(2, MBLK), 256, SMEM1>>>(x);

    // join: attn1 needs both gemm1 (main) and CSR (side)
    cudaStreamWaitEvent(0, s_join, 0);
    k_attn1<<<(N_NODES + 7) / 8, 256>>>(b1);
    k_gemm2_mma<<<dim3(2, MBLK), 256, SMEM2>>>();
    k_attn2<<<(N_NODES + 7) / 8, 256>>>(b2, out);
}